// round 4
// baseline (speedup 1.0000x reference)
#include <cuda_runtime.h>
#include <cuda_bf16.h>

// ---------------------------------------------------------------------------
// VQ-VAE forward, fp32 baseline.
// Shapes: B=16, C=128, x 256x256, latent 64x64, K=512 codes.
// Outputs concatenated in d_out: x_hat (16*3*256*256) | ze (16*128*64*64) | zq (same)
// ---------------------------------------------------------------------------

#define BATCH 16
#define CH    128
#define HLAT  64          // latent H=W
#define NPIX  (HLAT*HLAT) // 4096
#define XHAT_ELEMS (16*3*256*256)      // 3145728
#define ZE_ELEMS   (16*128*64*64)      // 8388608

// scratch buffers (static device globals; allocation inside kernel_launch is forbidden)
__device__ float g_A[16*128*128*128];  // 33.5M floats: e1 out / dt1 out
__device__ float g_B[ZE_ELEMS];
__device__ float g_C[ZE_ELEMS];
__device__ float g_D[ZE_ELEMS];
__device__ float g_T[ZE_ELEMS];

// ---------------------------------------------------------------------------
// e1: conv 3->128, k4 s2 p1, input 256x256 -> 128x128, ReLU
// ---------------------------------------------------------------------------
__global__ __launch_bounds__(256) void e1_k(const float* __restrict__ x,
                                            const float* __restrict__ w,
                                            const float* __restrict__ bias,
                                            float* __restrict__ out) {
    __shared__ float ws[128*3*16];
    for (int i = threadIdx.x; i < 128*3*16; i += 256) ws[i] = w[i];
    __syncthreads();
    int g = blockIdx.x * 256 + threadIdx.x;   // 33,554,432 total
    int ox = g & 127, oy = (g >> 7) & 127, co = (g >> 14) & 127, b = g >> 21;
    float acc = bias[co];
    int iy0 = 2*oy - 1, ix0 = 2*ox - 1;
    #pragma unroll
    for (int ci = 0; ci < 3; ci++) {
        const float* xp = x + (b*3 + ci) * 65536;
        const float* wp = ws + (co*3 + ci) * 16;
        #pragma unroll
        for (int ky = 0; ky < 4; ky++) {
            int iy = iy0 + ky;
            if ((unsigned)iy < 256u) {
                #pragma unroll
                for (int kx = 0; kx < 4; kx++) {
                    int ix = ix0 + kx;
                    if ((unsigned)ix < 256u)
                        acc = fmaf(xp[iy*256 + ix], wp[ky*4 + kx], acc);
                }
            }
        }
    }
    out[g] = fmaxf(acc, 0.f);
}

// ---------------------------------------------------------------------------
// e2: conv 128->128, k4 s2 p1, 128x128 -> 64x64, ReLU
// ---------------------------------------------------------------------------
__global__ __launch_bounds__(128) void conv4s2_k(const float* __restrict__ in,
                                                 const float* __restrict__ w,
                                                 const float* __restrict__ bias,
                                                 float* __restrict__ out) {
    const int co = threadIdx.x;
    const int ox0 = blockIdx.x * 8, oy0 = blockIdx.y * 8, b = blockIdx.z;
    __shared__ float s[8][18][18];
    float acc[64];
    {
        float bv = bias[co];
        #pragma unroll
        for (int i = 0; i < 64; i++) acc[i] = bv;
    }
    const int iy0 = oy0*2 - 1, ix0 = ox0*2 - 1;
    for (int cc = 0; cc < 128; cc += 8) {
        __syncthreads();
        for (int idx = co; idx < 8*324; idx += 128) {
            int ci = idx / 324, rr = idx % 324, r = rr / 18, cl = rr % 18;
            int iy = iy0 + r, ix = ix0 + cl;
            float v = 0.f;
            if ((unsigned)iy < 128u && (unsigned)ix < 128u)
                v = in[((b*128 + cc + ci) * 128 + iy) * 128 + ix];
            s[ci][r][cl] = v;
        }
        __syncthreads();
        #pragma unroll 1
        for (int ci = 0; ci < 8; ci++) {
            float wt[16];
            const float* wp = w + ((co*128) + cc + ci) * 16;
            #pragma unroll
            for (int k = 0; k < 16; k++) wt[k] = wp[k];
            #pragma unroll
            for (int py = 0; py < 8; py++) {
                #pragma unroll
                for (int ky = 0; ky < 4; ky++) {
                    float row[18];
                    #pragma unroll
                    for (int i = 0; i < 18; i++) row[i] = s[ci][2*py + ky][i];
                    #pragma unroll
                    for (int px = 0; px < 8; px++) {
                        float a = acc[py*8 + px];
                        a = fmaf(row[2*px + 0], wt[ky*4 + 0], a);
                        a = fmaf(row[2*px + 1], wt[ky*4 + 1], a);
                        a = fmaf(row[2*px + 2], wt[ky*4 + 2], a);
                        a = fmaf(row[2*px + 3], wt[ky*4 + 3], a);
                        acc[py*8 + px] = a;
                    }
                }
            }
        }
    }
    float* op = out + ((b*128 + co) * 64 + oy0) * 64 + ox0;
    #pragma unroll
    for (int py = 0; py < 8; py++)
        #pragma unroll
        for (int px = 0; px < 8; px++)
            op[py*64 + px] = fmaxf(acc[py*8 + px], 0.f);
}

// ---------------------------------------------------------------------------
// conv3x3, C=128, 64x64, pad 1. Optional ReLU on input read.
// ---------------------------------------------------------------------------
template<bool RELU_IN>
__global__ __launch_bounds__(128) void conv3x3_k(const float* __restrict__ in,
                                                 const float* __restrict__ w,
                                                 const float* __restrict__ bias,
                                                 float* __restrict__ out) {
    const int co = threadIdx.x;
    const int ox0 = blockIdx.x * 8, oy0 = blockIdx.y * 8, b = blockIdx.z;
    __shared__ float s[16][10][10];
    float acc[64];
    {
        float bv = bias[co];
        #pragma unroll
        for (int i = 0; i < 64; i++) acc[i] = bv;
    }
    for (int cc = 0; cc < 128; cc += 16) {
        __syncthreads();
        for (int idx = co; idx < 16*100; idx += 128) {
            int ci = idx / 100, rr = idx % 100, r = rr / 10, cl = rr % 10;
            int iy = oy0 - 1 + r, ix = ox0 - 1 + cl;
            float v = 0.f;
            if ((unsigned)iy < 64u && (unsigned)ix < 64u) {
                v = in[((b*128 + cc + ci) * 64 + iy) * 64 + ix];
                if (RELU_IN) v = fmaxf(v, 0.f);
            }
            s[ci][r][cl] = v;
        }
        __syncthreads();
        #pragma unroll 1
        for (int ci = 0; ci < 16; ci++) {
            float wt[9];
            const float* wp = w + ((co*128) + cc + ci) * 9;
            #pragma unroll
            for (int k = 0; k < 9; k++) wt[k] = wp[k];
            #pragma unroll
            for (int py = 0; py < 8; py++) {
                #pragma unroll
                for (int ky = 0; ky < 3; ky++) {
                    float row[10];
                    #pragma unroll
                    for (int i = 0; i < 10; i++) row[i] = s[ci][py + ky][i];
                    #pragma unroll
                    for (int px = 0; px < 8; px++) {
                        float a = acc[py*8 + px];
                        a = fmaf(row[px + 0], wt[ky*3 + 0], a);
                        a = fmaf(row[px + 1], wt[ky*3 + 1], a);
                        a = fmaf(row[px + 2], wt[ky*3 + 2], a);
                        acc[py*8 + px] = a;
                    }
                }
            }
        }
    }
    float* op = out + ((b*128 + co) * 64 + oy0) * 64 + ox0;
    #pragma unroll
    for (int py = 0; py < 8; py++)
        #pragma unroll
        for (int px = 0; px < 8; px++)
            op[py*64 + px] = acc[py*8 + px];
}

// ---------------------------------------------------------------------------
// conv1x1 with ReLU on input and residual add: out = res + (W @ relu(in) + b)
// ---------------------------------------------------------------------------
__global__ __launch_bounds__(128) void conv1x1_res_k(const float* __restrict__ in,
                                                     const float* __restrict__ w,
                                                     const float* __restrict__ bias,
                                                     const float* __restrict__ res,
                                                     float* __restrict__ out) {
    const int co = threadIdx.x;
    const int b = blockIdx.x >> 6;
    const int p0 = (blockIdx.x & 63) * 64;
    __shared__ float s[32][64];
    float acc[64];
    {
        float bv = bias[co];
        #pragma unroll
        for (int i = 0; i < 64; i++) acc[i] = bv;
    }
    for (int cc = 0; cc < 128; cc += 32) {
        __syncthreads();
        for (int idx = co; idx < 32*64; idx += 128) {
            int ci = idx >> 6, p = idx & 63;
            float v = in[(b*128 + cc + ci) * 4096 + p0 + p];
            s[ci][p] = fmaxf(v, 0.f);
        }
        __syncthreads();
        #pragma unroll 1
        for (int ci = 0; ci < 32; ci++) {
            float wv = w[co*128 + cc + ci];
            #pragma unroll
            for (int p = 0; p < 64; p++)
                acc[p] = fmaf(s[ci][p], wv, acc[p]);
        }
    }
    const float* rp = res + (b*128 + co) * 4096 + p0;
    float* op = out + (b*128 + co) * 4096 + p0;
    #pragma unroll
    for (int p = 0; p < 64; p++) op[p] = rp[p] + acc[p];
}

// ---------------------------------------------------------------------------
// VQ: replicate the reference numeric pipeline exactly:
//   d_k = (zz - 2*dot_k) + ee_k   evaluated in fp32 with that op tree,
//   dot_k = ascending-c fp32 FMA chain (cublas SGEMM k-loop order),
//   zz, ee in fp64 rounded once (zz is shared across k; ee is tiny),
//   argmin: strict fp32 <, first (lowest) index wins ties, like jnp.argmin.
// block: 256 threads, 64 consecutive positions
// ---------------------------------------------------------------------------
__global__ __launch_bounds__(256) void vq_k(const float* __restrict__ ze,
                                            const float* __restrict__ cb,
                                            float* __restrict__ zq) {
    const int b = blockIdx.x >> 6;
    const int p0 = (blockIdx.x & 63) * 64;
    __shared__ float zs[128][64];    // [c][pos]  32KB
    __shared__ float cs[16][128];    // 8KB
    __shared__ float zzs[64];
    __shared__ float ees[512];       // 2KB
    __shared__ float rb1[256]; __shared__ int ri1[256];
    __shared__ int   finalidx[64];
    const int t = threadIdx.x;
    const float* zb = ze + b * 128 * 4096 + p0;
    for (int idx = t; idx < 128*64; idx += 256) {
        int c = idx >> 6, p = idx & 63;
        zs[c][p] = zb[c*4096 + p];
    }
    // ee[k] = sum_c cb[k][c]^2 (fp64, rounded once)
    for (int k = t; k < 512; k += 256) {
        const float* cp = cb + k * 128;
        double acc = 0.0;
        for (int c = 0; c < 128; c++) { double e = (double)cp[c]; acc += e * e; }
        ees[k] = (float)acc;
    }
    __syncthreads();
    // zz[pos] = sum_c z^2 (fp64, rounded once; shared across k)
    if (t < 64) {
        double acc = 0.0;
        for (int c = 0; c < 128; c++) { double z = (double)zs[c][t]; acc += z * z; }
        zzs[t] = (float)acc;
    }
    __syncthreads();

    float b1 = 3.4e38f; int i1 = 0x7fffffff;
    const int pos = t & 63, cg = t >> 6;   // 4 code-groups per position
    const float zz = zzs[pos];
    for (int k0 = 0; k0 < 512; k0 += 16) {
        __syncthreads();
        for (int idx = t; idx < 16*128; idx += 256)
            cs[idx >> 7][idx & 127] = cb[k0*128 + idx];
        __syncthreads();
        for (int j = cg; j < 16; j += 4) {
            // dot: ascending-c fp32 FMA chain, no re-association
            float dot = 0.f;
            #pragma unroll 8
            for (int c = 0; c < 128; c++)
                dot = __fmaf_rn(zs[c][pos], cs[j][c], dot);
            int gidx = k0 + j;
            // d = (zz - 2*dot) + ee   -- reference op tree, fp32 roundings
            float d = __fadd_rn(__fsub_rn(zz, __fmul_rn(2.f, dot)), ees[gidx]);
            // strict <, ascending gidx within this thread -> first index wins ties
            if (d < b1) { b1 = d; i1 = gidx; }
        }
    }
    rb1[t] = b1; ri1[t] = i1;
    __syncthreads();
    if (t < 64) {
        // merge 4 groups: min d, tie -> lowest index (jnp.argmin semantics)
        float B1 = rb1[t]; int I1 = ri1[t];
        #pragma unroll
        for (int g = 1; g < 4; g++) {
            float v = rb1[t + 64*g]; int vi = ri1[t + 64*g];
            if (v < B1 || (v == B1 && vi < I1)) { B1 = v; I1 = vi; }
        }
        finalidx[t] = I1;
    }
    __syncthreads();
    float* zqb = zq + b * 128 * 4096 + p0;
    for (int idx = t; idx < 128*64; idx += 256) {
        int c = idx >> 6, p = idx & 63;
        zqb[c*4096 + p] = cb[finalidx[p]*128 + c];
    }
}

// ---------------------------------------------------------------------------
// dt1: ConvTranspose2d 128->128, k4 s2 p1, 64x64 -> 128x128, ReLU
// ---------------------------------------------------------------------------
__global__ __launch_bounds__(128) void dt1_k(const float* __restrict__ in,
                                             const float* __restrict__ w,
                                             const float* __restrict__ bias,
                                             float* __restrict__ out) {
    const int co = threadIdx.x;
    const int tx = blockIdx.x, ty = blockIdx.y, b = blockIdx.z;
    const int ox0 = tx * 8, oy0 = ty * 8;
    const int iyb = 4*ty - 1, ixb = 4*tx - 1;
    __shared__ float s[16][6][6];
    float acc[64];
    {
        float bv = bias[co];
        #pragma unroll
        for (int i = 0; i < 64; i++) acc[i] = bv;
    }
    for (int cc = 0; cc < 128; cc += 16) {
        __syncthreads();
        for (int idx = co; idx < 16*36; idx += 128) {
            int ci = idx / 36, rr = idx % 36, r = rr / 6, cl = rr % 6;
            int iy = iyb + r, ix = ixb + cl;
            float v = 0.f;
            if ((unsigned)iy < 64u && (unsigned)ix < 64u)
                v = in[((b*128 + cc + ci) << 12) + iy*64 + ix];
            s[ci][r][cl] = v;
        }
        __syncthreads();
        #pragma unroll 1
        for (int ci = 0; ci < 16; ci++) {
            float wt[16];
            const float* wp = w + (((cc + ci) * 128) + co) * 16;
            #pragma unroll
            for (int k = 0; k < 16; k++) wt[k] = wp[k];
            #pragma unroll
            for (int py = 0; py < 8; py++) {
                const int ky0 = 1 - (py & 1);
                const int q = (py + 1 - ky0) >> 1;
                float rH[6], rL[6];
                #pragma unroll
                for (int i = 0; i < 6; i++) { rH[i] = s[ci][q+1][i]; rL[i] = s[ci][q][i]; }
                #pragma unroll
                for (int px = 0; px < 8; px++) {
                    const int kx0 = 1 - (px & 1);
                    const int qx = (px + 1 - kx0) >> 1;
                    float a = acc[py*8 + px];
                    a = fmaf(rH[qx+1], wt[ky0*4 + kx0],           a);
                    a = fmaf(rH[qx],   wt[ky0*4 + kx0 + 2],       a);
                    a = fmaf(rL[qx+1], wt[(ky0+2)*4 + kx0],       a);
                    a = fmaf(rL[qx],   wt[(ky0+2)*4 + kx0 + 2],   a);
                    acc[py*8 + px] = a;
                }
            }
        }
    }
    float* op = out + ((b*128 + co) << 14) + oy0*128 + ox0;
    #pragma unroll
    for (int py = 0; py < 8; py++)
        #pragma unroll
        for (int px = 0; px < 8; px++)
            op[py*128 + px] = fmaxf(acc[py*8 + px], 0.f);
}

// ---------------------------------------------------------------------------
// dt2: ConvTranspose2d 128->3, k4 s2 p1, 128x128 -> 256x256 (no relu)
// ---------------------------------------------------------------------------
__global__ __launch_bounds__(256) void dt2_k(const float* __restrict__ in,
                                             const float* __restrict__ w,
                                             const float* __restrict__ bias,
                                             float* __restrict__ out) {
    __shared__ float ws[128*3*16];
    for (int i = threadIdx.x; i < 128*3*16; i += 256) ws[i] = w[i];
    __syncthreads();
    int g = blockIdx.x * 256 + threadIdx.x;   // 1,048,576 pixels
    int ox = g & 255, oy = (g >> 8) & 255, b = g >> 16;
    float a0 = bias[0], a1 = bias[1], a2 = bias[2];
    const int ky0 = (oy + 1) & 1, kx0 = (ox + 1) & 1;
    const int iyh = (oy + 1 - ky0) >> 1, ixh = (ox + 1 - kx0) >> 1;
    #pragma unroll 4
    for (int ci = 0; ci < 128; ci++) {
        const float* ip = in + ((b*128 + ci) << 14);
        const float* wp = ws + ci * 48;
        #pragma unroll
        for (int dy = 0; dy < 2; dy++) {
            int iy = iyh - dy, ky = ky0 + 2*dy;
            if ((unsigned)iy < 128u) {
                #pragma unroll
                for (int dx = 0; dx < 2; dx++) {
                    int ix = ixh - dx, kx = kx0 + 2*dx;
                    if ((unsigned)ix < 128u) {
                        float v = ip[iy*128 + ix];
                        int wk = ky*4 + kx;
                        a0 = fmaf(v, wp[wk],      a0);
                        a1 = fmaf(v, wp[16 + wk], a1);
                        a2 = fmaf(v, wp[32 + wk], a2);
                    }
                }
            }
        }
    }
    int sp = oy*256 + ox;
    out[(b*3 + 0) * 65536 + sp] = a0;
    out[(b*3 + 1) * 65536 + sp] = a1;
    out[(b*3 + 2) * 65536 + sp] = a2;
}

// ---------------------------------------------------------------------------

extern "C" void kernel_launch(void* const* d_in, const int* in_sizes, int n_in,
                              void* d_out, int out_size) {
    const float* x      = (const float*)d_in[0];
    const float* e1_w   = (const float*)d_in[1];  const float* e1_b = (const float*)d_in[2];
    const float* e2_w   = (const float*)d_in[3];  const float* e2_b = (const float*)d_in[4];
    const float* e3_w   = (const float*)d_in[5];  const float* e3_b = (const float*)d_in[6];
    const float* er1a_w = (const float*)d_in[7];  const float* er1a_b = (const float*)d_in[8];
    const float* er1b_w = (const float*)d_in[9];  const float* er1b_b = (const float*)d_in[10];
    const float* er2a_w = (const float*)d_in[11]; const float* er2a_b = (const float*)d_in[12];
    const float* er2b_w = (const float*)d_in[13]; const float* er2b_b = (const float*)d_in[14];
    const float* codebook = (const float*)d_in[15];
    const float* d1_w   = (const float*)d_in[16]; const float* d1_b = (const float*)d_in[17];
    const float* dr1a_w = (const float*)d_in[18]; const float* dr1a_b = (const float*)d_in[19];
    const float* dr1b_w = (const float*)d_in[20]; const float* dr1b_b = (const float*)d_in[21];
    const float* dr2a_w = (const float*)d_in[22]; const float* dr2a_b = (const float*)d_in[23];
    const float* dr2b_w = (const float*)d_in[24]; const float* dr2b_b = (const float*)d_in[25];
    const float* dt1_w  = (const float*)d_in[26]; const float* dt1_b = (const float*)d_in[27];
    const float* dt2_w  = (const float*)d_in[28]; const float* dt2_b = (const float*)d_in[29];

    float* out   = (float*)d_out;
    float* xhat  = out;
    float* ze    = out + XHAT_ELEMS;
    float* zq    = out + XHAT_ELEMS + ZE_ELEMS;

    float* A; cudaGetSymbolAddress((void**)&A, g_A);
    float* Bf; cudaGetSymbolAddress((void**)&Bf, g_B);
    float* Cf; cudaGetSymbolAddress((void**)&Cf, g_C);
    float* Df; cudaGetSymbolAddress((void**)&Df, g_D);
    float* Tf; cudaGetSymbolAddress((void**)&Tf, g_T);

    dim3 tile64(8, 8, BATCH);     // 8x8 tiles over 64x64
    dim3 tile128(16, 16, BATCH);  // 8x8 tiles over 128x128

    // encoder
    e1_k<<<(16*128*128*128)/256, 256>>>(x, e1_w, e1_b, A);
    conv4s2_k<<<tile64, 128>>>(A, e2_w, e2_b, Bf);
    conv3x3_k<false><<<tile64, 128>>>(Bf, e3_w, e3_b, Cf);
    // resblock 1: C -> D
    conv3x3_k<true><<<tile64, 128>>>(Cf, er1a_w, er1a_b, Tf);
    conv1x1_res_k<<<16*64, 128>>>(Tf, er1b_w, er1b_b, Cf, Df);
    // resblock 2: D -> ze (written directly into d_out)
    conv3x3_k<true><<<tile64, 128>>>(Df, er2a_w, er2a_b, Tf);
    conv1x1_res_k<<<16*64, 128>>>(Tf, er2b_w, er2b_b, Df, ze);
    // VQ: ze -> zq
    vq_k<<<16*64, 256>>>(ze, codebook, zq);
    // decoder (dec_in == zq)
    conv3x3_k<false><<<tile64, 128>>>(zq, d1_w, d1_b, Cf);
    conv3x3_k<true><<<tile64, 128>>>(Cf, dr1a_w, dr1a_b, Tf);
    conv1x1_res_k<<<16*64, 128>>>(Tf, dr1b_w, dr1b_b, Cf, Df);
    conv3x3_k<true><<<tile64, 128>>>(Df, dr2a_w, dr2a_b, Tf);
    conv1x1_res_k<<<16*64, 128>>>(Tf, dr2b_w, dr2b_b, Df, Bf);
    dt1_k<<<tile128, 128>>>(Bf, dt1_w, dt1_b, A);
    dt2_k<<<(16*256*256)/256, 256>>>(A, dt2_w, dt2_b, xhat);
}

// round 7
// speedup vs baseline: 1.6878x; 1.6878x over previous
#include <cuda_runtime.h>
#include <cuda_bf16.h>

// ---------------------------------------------------------------------------
// VQ-VAE forward, fp32, LDS-optimized scalar kernels.
// Shapes: B=16, C=128, x 256x256, latent 64x64, K=512 codes.
// d_out: x_hat (16*3*256*256) | ze (16*128*64*64) | zq (same)
// ---------------------------------------------------------------------------

#define BATCH 16
#define XHAT_ELEMS (16*3*256*256)      // 3145728
#define ZE_ELEMS   (16*128*64*64)      // 8388608

// scratch buffers
__device__ float g_A[16*128*128*128];  // e1 out / dt1 out
__device__ float g_B[ZE_ELEMS];
__device__ float g_C[ZE_ELEMS];
__device__ float g_D[ZE_ELEMS];
__device__ float g_T[ZE_ELEMS];
__device__ float g_W[1474560];         // transposed weights

// transposed-weight layout offsets (floats)
#define W3_OFF(i)  ((i) * 147456)          // 6 conv3x3 layers
#define WE2_OFF    884736                  // e2 (k=16)
#define WDT1_OFF   1146880                 // dt1 (k=16)
#define W1_OFF(i)  (1409024 + (i) * 16384) // 4 conv1x1 layers

// ---------------------------------------------------------------------------
// weight transposes: make per-ci weight reads coalesced over co
// ---------------------------------------------------------------------------
__global__ __launch_bounds__(256) void tpose_ock(const float* __restrict__ w,
                                                 float* __restrict__ wt, int K) {
    // w[co][ci][k] -> wt[(ci*K+k)*128 + co]
    int i = blockIdx.x * 256 + threadIdx.x;      // 128*128*K total
    int co = i / (128 * K);
    int r  = i % (128 * K);                      // r = ci*K + k
    wt[r * 128 + co] = w[i];
}
__global__ __launch_bounds__(256) void tpose_iok(const float* __restrict__ w,
                                                 float* __restrict__ wt, int K) {
    // w[ci][co][k] -> wt[(ci*K+k)*128 + co]
    int i = blockIdx.x * 256 + threadIdx.x;
    int ci = i / (128 * K);
    int r  = i % (128 * K);
    int co = r / K, k = r % K;
    wt[(ci * K + k) * 128 + co] = w[i];
}

// ---------------------------------------------------------------------------
// e1: conv 3->128, k4 s2 p1, 256x256 -> 128x128, ReLU
// ---------------------------------------------------------------------------
__global__ __launch_bounds__(256) void e1_k(const float* __restrict__ x,
                                            const float* __restrict__ w,
                                            const float* __restrict__ bias,
                                            float* __restrict__ out) {
    __shared__ float ws[128*3*16];
    for (int i = threadIdx.x; i < 128*3*16; i += 256) ws[i] = w[i];
    __syncthreads();
    int g = blockIdx.x * 256 + threadIdx.x;
    int ox = g & 127, oy = (g >> 7) & 127, co = (g >> 14) & 127, b = g >> 21;
    float acc = bias[co];
    int iy0 = 2*oy - 1, ix0 = 2*ox - 1;
    #pragma unroll
    for (int ci = 0; ci < 3; ci++) {
        const float* xp = x + (b*3 + ci) * 65536;
        const float* wp = ws + (co*3 + ci) * 16;
        #pragma unroll
        for (int ky = 0; ky < 4; ky++) {
            int iy = iy0 + ky;
            if ((unsigned)iy < 256u) {
                #pragma unroll
                for (int kx = 0; kx < 4; kx++) {
                    int ix = ix0 + kx;
                    if ((unsigned)ix < 256u)
                        acc = fmaf(xp[iy*256 + ix], wp[ky*4 + kx], acc);
                }
            }
        }
    }
    out[g] = fmaxf(acc, 0.f);
}

// ---------------------------------------------------------------------------
// e2: conv 128->128, k4 s2 p1, 128x128 -> 64x64, ReLU.  wT[(ci*16+k)*128+co]
// ---------------------------------------------------------------------------
__global__ __launch_bounds__(128) void conv4s2_k(const float* __restrict__ in,
                                                 const float* __restrict__ wT,
                                                 const float* __restrict__ bias,
                                                 float* __restrict__ out) {
    const int co = threadIdx.x;
    const int ox0 = blockIdx.x * 8, oy0 = blockIdx.y * 8, b = blockIdx.z;
    __shared__ float s[8][18][20];   // rows padded to 20 floats (80B, 16B-aligned)
    float acc[64];
    {
        float bv = bias[co];
        #pragma unroll
        for (int i = 0; i < 64; i++) acc[i] = bv;
    }
    const int iy0 = oy0*2 - 1, ix0 = ox0*2 - 1;
    for (int cc = 0; cc < 128; cc += 8) {
        __syncthreads();
        for (int idx = co; idx < 8*324; idx += 128) {
            int ci = idx / 324, rr = idx % 324, r = rr / 18, cl = rr % 18;
            int iy = iy0 + r, ix = ix0 + cl;
            float v = 0.f;
            if ((unsigned)iy < 128u && (unsigned)ix < 128u)
                v = in[((b*128 + cc + ci) * 128 + iy) * 128 + ix];
            s[ci][r][cl] = v;
        }
        __syncthreads();
        #pragma unroll 1
        for (int ci = 0; ci < 8; ci++) {
            float wt[16];
            const float* wp = wT + (cc + ci) * 16 * 128 + co;
            #pragma unroll
            for (int k = 0; k < 16; k++) wt[k] = wp[k*128];
            #pragma unroll
            for (int r = 0; r < 18; r++) {
                float4 f0 = *(const float4*)&s[ci][r][0];
                float4 f1 = *(const float4*)&s[ci][r][4];
                float4 f2 = *(const float4*)&s[ci][r][8];
                float4 f3 = *(const float4*)&s[ci][r][12];
                float4 f4 = *(const float4*)&s[ci][r][16];
                float row[18] = {f0.x,f0.y,f0.z,f0.w, f1.x,f1.y,f1.z,f1.w,
                                 f2.x,f2.y,f2.z,f2.w, f3.x,f3.y,f3.z,f3.w,
                                 f4.x,f4.y};
                #pragma unroll
                for (int ky = 0; ky < 4; ky++) {
                    if (((r - ky) & 1) == 0) {
                        int py = (r - ky) >> 1;
                        if (py >= 0 && py < 8) {
                            #pragma unroll
                            for (int px = 0; px < 8; px++) {
                                float a = acc[py*8 + px];
                                a = fmaf(row[2*px + 0], wt[ky*4 + 0], a);
                                a = fmaf(row[2*px + 1], wt[ky*4 + 1], a);
                                a = fmaf(row[2*px + 2], wt[ky*4 + 2], a);
                                a = fmaf(row[2*px + 3], wt[ky*4 + 3], a);
                                acc[py*8 + px] = a;
                            }
                        }
                    }
                }
            }
        }
    }
    float* op = out + ((b*128 + co) * 64 + oy0) * 64 + ox0;
    #pragma unroll
    for (int py = 0; py < 8; py++)
        #pragma unroll
        for (int px = 0; px < 8; px++)
            op[py*64 + px] = fmaxf(acc[py*8 + px], 0.f);
}

// ---------------------------------------------------------------------------
// conv3x3, C=128, 64x64, pad 1. Optional ReLU on input.  wT[(ci*9+k)*128+co]
// ---------------------------------------------------------------------------
template<bool RELU_IN>
__global__ __launch_bounds__(128) void conv3x3_k(const float* __restrict__ in,
                                                 const float* __restrict__ wT,
                                                 const float* __restrict__ bias,
                                                 float* __restrict__ out) {
    const int co = threadIdx.x;
    const int ox0 = blockIdx.x * 8, oy0 = blockIdx.y * 8, b = blockIdx.z;
    __shared__ float s[16][10][12];  // rows padded to 12 floats (48B, 16B-aligned)
    float acc[64];
    {
        float bv = bias[co];
        #pragma unroll
        for (int i = 0; i < 64; i++) acc[i] = bv;
    }
    for (int cc = 0; cc < 128; cc += 16) {
        __syncthreads();
        for (int idx = co; idx < 16*100; idx += 128) {
            int ci = idx / 100, rr = idx % 100, r = rr / 10, cl = rr % 10;
            int iy = oy0 - 1 + r, ix = ox0 - 1 + cl;
            float v = 0.f;
            if ((unsigned)iy < 64u && (unsigned)ix < 64u) {
                v = in[((b*128 + cc + ci) * 64 + iy) * 64 + ix];
                if (RELU_IN) v = fmaxf(v, 0.f);
            }
            s[ci][r][cl] = v;
        }
        __syncthreads();
        #pragma unroll 1
        for (int ci = 0; ci < 16; ci++) {
            float wt[9];
            const float* wp = wT + (cc + ci) * 9 * 128 + co;
            #pragma unroll
            for (int k = 0; k < 9; k++) wt[k] = wp[k*128];
            #pragma unroll
            for (int r = 0; r < 10; r++) {
                float4 f0 = *(const float4*)&s[ci][r][0];
                float4 f1 = *(const float4*)&s[ci][r][4];
                float4 f2 = *(const float4*)&s[ci][r][8];
                float row[10] = {f0.x,f0.y,f0.z,f0.w, f1.x,f1.y,f1.z,f1.w,
                                 f2.x,f2.y};
                #pragma unroll
                for (int ky = 0; ky < 3; ky++) {
                    int py = r - ky;
                    if (py >= 0 && py < 8) {
                        #pragma unroll
                        for (int px = 0; px < 8; px++) {
                            float a = acc[py*8 + px];
                            a = fmaf(row[px + 0], wt[ky*3 + 0], a);
                            a = fmaf(row[px + 1], wt[ky*3 + 1], a);
                            a = fmaf(row[px + 2], wt[ky*3 + 2], a);
                            acc[py*8 + px] = a;
                        }
                    }
                }
            }
        }
    }
    float* op = out + ((b*128 + co) * 64 + oy0) * 64 + ox0;
    #pragma unroll
    for (int py = 0; py < 8; py++)
        #pragma unroll
        for (int px = 0; px < 8; px++)
            op[py*64 + px] = acc[py*8 + px];
}

// ---------------------------------------------------------------------------
// conv1x1 + input ReLU + residual: out = res + (W @ relu(in) + b)
// wT[ci*128+co]
// ---------------------------------------------------------------------------
__global__ __launch_bounds__(128) void conv1x1_res_k(const float* __restrict__ in,
                                                     const float* __restrict__ wT,
                                                     const float* __restrict__ bias,
                                                     const float* __restrict__ res,
                                                     float* __restrict__ out) {
    const int co = threadIdx.x;
    const int b = blockIdx.x >> 6;
    const int p0 = (blockIdx.x & 63) * 64;
    __shared__ float s[32][64];
    float acc[64];
    {
        float bv = bias[co];
        #pragma unroll
        for (int i = 0; i < 64; i++) acc[i] = bv;
    }
    for (int cc = 0; cc < 128; cc += 32) {
        __syncthreads();
        for (int idx = co; idx < 32*64; idx += 128) {
            int ci = idx >> 6, p = idx & 63;
            float v = in[(b*128 + cc + ci) * 4096 + p0 + p];
            s[ci][p] = fmaxf(v, 0.f);
        }
        __syncthreads();
        #pragma unroll 1
        for (int ci = 0; ci < 32; ci++) {
            float wv = wT[(cc + ci) * 128 + co];
            const float4* sp = (const float4*)s[ci];
            #pragma unroll
            for (int p4 = 0; p4 < 16; p4++) {
                float4 v = sp[p4];
                acc[4*p4 + 0] = fmaf(v.x, wv, acc[4*p4 + 0]);
                acc[4*p4 + 1] = fmaf(v.y, wv, acc[4*p4 + 1]);
                acc[4*p4 + 2] = fmaf(v.z, wv, acc[4*p4 + 2]);
                acc[4*p4 + 3] = fmaf(v.w, wv, acc[4*p4 + 3]);
            }
        }
    }
    const float* rp = res + (b*128 + co) * 4096 + p0;
    float* op = out + (b*128 + co) * 4096 + p0;
    #pragma unroll
    for (int p = 0; p < 64; p++) op[p] = rp[p] + acc[p];
}

// ---------------------------------------------------------------------------
// VQ: replicate reference numeric pipeline exactly.
//   d_k = (zz - 2*dot_k) + ee_k, fp32 op tree; dot = ascending-c fp32 FMA chain;
//   strict <, lowest index wins ties. 4-code blocking + float4 codebook loads
//   (identical accumulation order per code).
// ---------------------------------------------------------------------------
__global__ __launch_bounds__(256) void vq_k(const float* __restrict__ ze,
                                            const float* __restrict__ cb,
                                            float* __restrict__ zq) {
    const int b = blockIdx.x >> 6;
    const int p0 = (blockIdx.x & 63) * 64;
    __shared__ float zs[128][64];    // [c][pos]
    __shared__ float cs[16][128];
    __shared__ float zzs[64];
    __shared__ float ees[512];
    __shared__ float rb1[256]; __shared__ int ri1[256];
    __shared__ int   finalidx[64];
    const int t = threadIdx.x;
    const float* zb = ze + b * 128 * 4096 + p0;
    for (int idx = t; idx < 128*64; idx += 256) {
        int c = idx >> 6, p = idx & 63;
        zs[c][p] = zb[c*4096 + p];
    }
    for (int k = t; k < 512; k += 256) {
        const float* cp = cb + k * 128;
        double acc = 0.0;
        for (int c = 0; c < 128; c++) { double e = (double)cp[c]; acc += e * e; }
        ees[k] = (float)acc;
    }
    __syncthreads();
    if (t < 64) {
        double acc = 0.0;
        for (int c = 0; c < 128; c++) { double z = (double)zs[c][t]; acc += z * z; }
        zzs[t] = (float)acc;
    }
    __syncthreads();

    float b1 = 3.4e38f; int i1 = 0x7fffffff;
    const int pos = t & 63, cg = t >> 6;   // thread handles codes j = cg + 4m
    const float zz = zzs[pos];
    for (int k0 = 0; k0 < 512; k0 += 16) {
        __syncthreads();
        for (int idx = t; idx < 16*128; idx += 256)
            cs[idx >> 7][idx & 127] = cb[k0*128 + idx];
        __syncthreads();
        float dot0 = 0.f, dot1 = 0.f, dot2 = 0.f, dot3 = 0.f;
        const float4* e0 = (const float4*)cs[cg + 0];
        const float4* e1 = (const float4*)cs[cg + 4];
        const float4* e2 = (const float4*)cs[cg + 8];
        const float4* e3 = (const float4*)cs[cg + 12];
        #pragma unroll 4
        for (int c4 = 0; c4 < 32; c4++) {
            float z0 = zs[4*c4 + 0][pos];
            float z1 = zs[4*c4 + 1][pos];
            float z2 = zs[4*c4 + 2][pos];
            float z3 = zs[4*c4 + 3][pos];
            float4 a = e0[c4], bb = e1[c4], cA = e2[c4], dd = e3[c4];
            dot0 = __fmaf_rn(z0, a.x, dot0);  dot0 = __fmaf_rn(z1, a.y, dot0);
            dot0 = __fmaf_rn(z2, a.z, dot0);  dot0 = __fmaf_rn(z3, a.w, dot0);
            dot1 = __fmaf_rn(z0, bb.x, dot1); dot1 = __fmaf_rn(z1, bb.y, dot1);
            dot1 = __fmaf_rn(z2, bb.z, dot1); dot1 = __fmaf_rn(z3, bb.w, dot1);
            dot2 = __fmaf_rn(z0, cA.x, dot2); dot2 = __fmaf_rn(z1, cA.y, dot2);
            dot2 = __fmaf_rn(z2, cA.z, dot2); dot2 = __fmaf_rn(z3, cA.w, dot2);
            dot3 = __fmaf_rn(z0, dd.x, dot3); dot3 = __fmaf_rn(z1, dd.y, dot3);
            dot3 = __fmaf_rn(z2, dd.z, dot3); dot3 = __fmaf_rn(z3, dd.w, dot3);
        }
        // update in ascending gidx order (j = cg, cg+4, cg+8, cg+12)
        float dts[4] = {dot0, dot1, dot2, dot3};
        #pragma unroll
        for (int m = 0; m < 4; m++) {
            int gidx = k0 + cg + 4*m;
            float d = __fadd_rn(__fsub_rn(zz, __fmul_rn(2.f, dts[m])), ees[gidx]);
            if (d < b1) { b1 = d; i1 = gidx; }
        }
    }
    rb1[t] = b1; ri1[t] = i1;
    __syncthreads();
    if (t < 64) {
        float B1 = rb1[t]; int I1 = ri1[t];
        #pragma unroll
        for (int g = 1; g < 4; g++) {
            float v = rb1[t + 64*g]; int vi = ri1[t + 64*g];
            if (v < B1 || (v == B1 && vi < I1)) { B1 = v; I1 = vi; }
        }
        finalidx[t] = I1;
    }
    __syncthreads();
    float* zqb = zq + b * 128 * 4096 + p0;
    for (int idx = t; idx < 128*64; idx += 256) {
        int c = idx >> 6, p = idx & 63;
        zqb[c*4096 + p] = cb[finalidx[p]*128 + c];
    }
}

// ---------------------------------------------------------------------------
// dt1: ConvTranspose2d 128->128, k4 s2 p1, 64x64 -> 128x128, ReLU
// wT[(ci*16+k)*128+co]
// ---------------------------------------------------------------------------
__global__ __launch_bounds__(128) void dt1_k(const float* __restrict__ in,
                                             const float* __restrict__ wT,
                                             const float* __restrict__ bias,
                                             float* __restrict__ out) {
    const int co = threadIdx.x;
    const int tx = blockIdx.x, ty = blockIdx.y, b = blockIdx.z;
    const int ox0 = tx * 8, oy0 = ty * 8;
    const int iyb = 4*ty - 1, ixb = 4*tx - 1;
    __shared__ float s[16][6][8];   // rows padded to 8 floats (32B aligned)
    float acc[64];
    {
        float bv = bias[co];
        #pragma unroll
        for (int i = 0; i < 64; i++) acc[i] = bv;
    }
    for (int cc = 0; cc < 128; cc += 16) {
        __syncthreads();
        for (int idx = co; idx < 16*36; idx += 128) {
            int ci = idx / 36, rr = idx % 36, r = rr / 6, cl = rr % 6;
            int iy = iyb + r, ix = ixb + cl;
            float v = 0.f;
            if ((unsigned)iy < 64u && (unsigned)ix < 64u)
                v = in[((b*128 + cc + ci) << 12) + iy*64 + ix];
            s[ci][r][cl] = v;
        }
        __syncthreads();
        #pragma unroll 1
        for (int ci = 0; ci < 16; ci++) {
            float wt[16];
            const float* wp = wT + (cc + ci) * 16 * 128 + co;
            #pragma unroll
            for (int k = 0; k < 16; k++) wt[k] = wp[k*128];
            #pragma unroll
            for (int py = 0; py < 8; py++) {
                const int ky0 = 1 - (py & 1);
                const int q = (py + 1 - ky0) >> 1;
                float4 h0 = *(const float4*)&s[ci][q+1][0];
                float4 h1 = *(const float4*)&s[ci][q+1][4];
                float4 l0 = *(const float4*)&s[ci][q][0];
                float4 l1 = *(const float4*)&s[ci][q][4];
                float rH[6] = {h0.x, h0.y, h0.z, h0.w, h1.x, h1.y};
                float rL[6] = {l0.x, l0.y, l0.z, l0.w, l1.x, l1.y};
                #pragma unroll
                for (int px = 0; px < 8; px++) {
                    const int kx0 = 1 - (px & 1);
                    const int qx = (px + 1 - kx0) >> 1;
                    float a = acc[py*8 + px];
                    a = fmaf(rH[qx+1], wt[ky0*4 + kx0],           a);
                    a = fmaf(rH[qx],   wt[ky0*4 + kx0 + 2],       a);
                    a = fmaf(rL[qx+1], wt[(ky0+2)*4 + kx0],       a);
                    a = fmaf(rL[qx],   wt[(ky0+2)*4 + kx0 + 2],   a);
                    acc[py*8 + px] = a;
                }
            }
        }
    }
    float* op = out + ((b*128 + co) << 14) + oy0*128 + ox0;
    #pragma unroll
    for (int py = 0; py < 8; py++)
        #pragma unroll
        for (int px = 0; px < 8; px++)
            op[py*128 + px] = fmaxf(acc[py*8 + px], 0.f);
}

// ---------------------------------------------------------------------------
// dt2: ConvTranspose2d 128->3, k4 s2 p1, 128x128 -> 256x256
// ---------------------------------------------------------------------------
__global__ __launch_bounds__(256) void dt2_k(const float* __restrict__ in,
                                             const float* __restrict__ w,
                                             const float* __restrict__ bias,
                                             float* __restrict__ out) {
    __shared__ float ws[128*3*16];
    for (int i = threadIdx.x; i < 128*3*16; i += 256) ws[i] = w[i];
    __syncthreads();
    int g = blockIdx.x * 256 + threadIdx.x;
    int ox = g & 255, oy = (g >> 8) & 255, b = g >> 16;
    float a0 = bias[0], a1 = bias[1], a2 = bias[2];
    const int ky0 = (oy + 1) & 1, kx0 = (ox + 1) & 1;
    const int iyh = (oy + 1 - ky0) >> 1, ixh = (ox + 1 - kx0) >> 1;
    #pragma unroll 4
    for (int ci = 0; ci < 128; ci++) {
        const float* ip = in + ((b*128 + ci) << 14);
        const float* wp = ws + ci * 48;
        #pragma unroll
        for (int dy = 0; dy < 2; dy++) {
            int iy = iyh - dy, ky = ky0 + 2*dy;
            if ((unsigned)iy < 128u) {
                #pragma unroll
                for (int dx = 0; dx < 2; dx++) {
                    int ix = ixh - dx, kx = kx0 + 2*dx;
                    if ((unsigned)ix < 128u) {
                        float v = ip[iy*128 + ix];
                        int wk = ky*4 + kx;
                        a0 = fmaf(v, wp[wk],      a0);
                        a1 = fmaf(v, wp[16 + wk], a1);
                        a2 = fmaf(v, wp[32 + wk], a2);
                    }
                }
            }
        }
    }
    int sp = oy*256 + ox;
    out[(b*3 + 0) * 65536 + sp] = a0;
    out[(b*3 + 1) * 65536 + sp] = a1;
    out[(b*3 + 2) * 65536 + sp] = a2;
}

// ---------------------------------------------------------------------------

extern "C" void kernel_launch(void* const* d_in, const int* in_sizes, int n_in,
                              void* d_out, int out_size) {
    const float* x      = (const float*)d_in[0];
    const float* e1_w   = (const float*)d_in[1];  const float* e1_b = (const float*)d_in[2];
    const float* e2_w   = (const float*)d_in[3];  const float* e2_b = (const float*)d_in[4];
    const float* e3_w   = (const float*)d_in[5];  const float* e3_b = (const float*)d_in[6];
    const float* er1a_w = (const float*)d_in[7];  const float* er1a_b = (const float*)d_in[8];
    const float* er1b_w = (const float*)d_in[9];  const float* er1b_b = (const float*)d_in[10];
    const float* er2a_w = (const float*)d_in[11]; const float* er2a_b = (const float*)d_in[12];
    const float* er2b_w = (const float*)d_in[13]; const float* er2b_b = (const float*)d_in[14];
    const float* codebook = (const float*)d_in[15];
    const float* d1_w   = (const float*)d_in[16]; const float* d1_b = (const float*)d_in[17];
    const float* dr1a_w = (const float*)d_in[18]; const float* dr1a_b = (const float*)d_in[19];
    const float* dr1b_w = (const float*)d_in[20]; const float* dr1b_b = (const float*)d_in[21];
    const float* dr2a_w = (const float*)d_in[22]; const float* dr2a_b = (const float*)d_in[23];
    const float* dr2b_w = (const float*)d_in[24]; const float* dr2b_b = (const float*)d_in[25];
    const float* dt1_w  = (const float*)d_in[26]; const float* dt1_b = (const float*)d_in[27];
    const float* dt2_w  = (const float*)d_in[28]; const float* dt2_b = (const float*)d_in[29];

    float* out   = (float*)d_out;
    float* xhat  = out;
    float* ze    = out + XHAT_ELEMS;
    float* zq    = out + XHAT_ELEMS + ZE_ELEMS;

    float* A;  cudaGetSymbolAddress((void**)&A,  g_A);
    float* Bf; cudaGetSymbolAddress((void**)&Bf, g_B);
    float* Cf; cudaGetSymbolAddress((void**)&Cf, g_C);
    float* Df; cudaGetSymbolAddress((void**)&Df, g_D);
    float* Tf; cudaGetSymbolAddress((void**)&Tf, g_T);
    float* W;  cudaGetSymbolAddress((void**)&W,  g_W);

    // weight transposes (cheap; run each launch, graph-capturable)
    tpose_ock<<<576, 256>>>(e3_w,   W + W3_OFF(0), 9);
    tpose_ock<<<576, 256>>>(er1a_w, W + W3_OFF(1), 9);
    tpose_ock<<<576, 256>>>(er2a_w, W + W3_OFF(2), 9);
    tpose_ock<<<576, 256>>>(d1_w,   W + W3_OFF(3), 9);
    tpose_ock<<<576, 256>>>(dr1a_w, W + W3_OFF(4), 9);
    tpose_ock<<<576, 256>>>(dr2a_w, W + W3_OFF(5), 9);
    tpose_ock<<<1024, 256>>>(e2_w,  W + WE2_OFF, 16);
    tpose_iok<<<1024, 256>>>(dt1_w, W + WDT1_OFF, 16);
    tpose_ock<<<64, 256>>>(er1b_w,  W + W1_OFF(0), 1);
    tpose_ock<<<64, 256>>>(er2b_w,  W + W1_OFF(1), 1);
    tpose_ock<<<64, 256>>>(dr1b_w,  W + W1_OFF(2), 1);
    tpose_ock<<<64, 256>>>(dr2b_w,  W + W1_OFF(3), 1);

    dim3 tile64(8, 8, BATCH);
    dim3 tile128(16, 16, BATCH);

    // encoder
    e1_k<<<(16*128*128*128)/256, 256>>>(x, e1_w, e1_b, A);
    conv4s2_k<<<tile64, 128>>>(A, W + WE2_OFF, e2_b, Bf);
    conv3x3_k<false><<<tile64, 128>>>(Bf, W + W3_OFF(0), e3_b, Cf);
    conv3x3_k<true><<<tile64, 128>>>(Cf, W + W3_OFF(1), er1a_b, Tf);
    conv1x1_res_k<<<16*64, 128>>>(Tf, W + W1_OFF(0), er1b_b, Cf, Df);
    conv3x3_k<true><<<tile64, 128>>>(Df, W + W3_OFF(2), er2a_b, Tf);
    conv1x1_res_k<<<16*64, 128>>>(Tf, W + W1_OFF(1), er2b_b, Df, ze);
    // VQ
    vq_k<<<16*64, 256>>>(ze, codebook, zq);
    // decoder (dec_in == zq)
    conv3x3_k<false><<<tile64, 128>>>(zq, W + W3_OFF(3), d1_b, Cf);
    conv3x3_k<true><<<tile64, 128>>>(Cf, W + W3_OFF(4), dr1a_b, Tf);
    conv1x1_res_k<<<16*64, 128>>>(Tf, W + W1_OFF(2), dr1b_b, Cf, Df);
    conv3x3_k<true><<<tile64, 128>>>(Df, W + W3_OFF(5), dr2a_b, Tf);
    conv1x1_res_k<<<16*64, 128>>>(Tf, W + W1_OFF(3), dr2b_b, Df, Bf);
    dt1_k<<<tile128, 128>>>(Bf, W + WDT1_OFF, dt1_b, A);
    dt2_k<<<(16*256*256)/256, 256>>>(A, dt2_w, dt2_b, xhat);
}

// round 12
// speedup vs baseline: 1.7710x; 1.0493x over previous
#include <cuda_runtime.h>
#include <cuda_bf16.h>
#include <cstdint>

// ---------------------------------------------------------------------------
// VQ-VAE forward. Encoder: fp32 scalar (bit-stable for VQ). Decoder 3x3 convs:
// warp-level mma.sync bf16 hi/lo split (3-pass). No tcgen05 (target sm_103).
// d_out: x_hat (16*3*256*256) | ze (16*128*64*64) | zq (same)
// ---------------------------------------------------------------------------

#define BATCH 16
#define XHAT_ELEMS (16*3*256*256)
#define ZE_ELEMS   (16*128*64*64)

__device__ float g_A[16*128*128*128];
__device__ float g_B[ZE_ELEMS];
__device__ float g_C[ZE_ELEMS];
__device__ float g_D[ZE_ELEMS];
__device__ float g_T[ZE_ELEMS];
__device__ float g_W[1474560];             // scalar transposed weights
__device__ __nv_bfloat16 g_Hi[ZE_ELEMS];   // NHWC hi plane
__device__ __nv_bfloat16 g_Lo[ZE_ELEMS];   // NHWC lo plane
__device__ uint4 g_WT[3*9*65536/16];       // mma weights: 3 layers x 9 taps x (hi32KB|lo32KB)

#define W3_OFF(i)  ((i) * 147456)
#define WE2_OFF    884736
#define WDT1_OFF   1146880
#define W1_OFF(i)  (1409024 + (i) * 16384)

// ============================ mma helpers ==================================
__device__ __forceinline__ uint32_t smem_u32(const void* p) {
    uint32_t a;
    asm("{ .reg .u64 t; cvta.to.shared.u64 t, %1; cvt.u32.u64 %0, t; }" : "=r"(a) : "l"(p));
    return a;
}
__device__ __forceinline__ void ldsm_x4(uint32_t* r, uint32_t addr) {
    asm volatile("ldmatrix.sync.aligned.m8n8.x4.shared.b16 {%0,%1,%2,%3}, [%4];"
        : "=r"(r[0]), "=r"(r[1]), "=r"(r[2]), "=r"(r[3]) : "r"(addr));
}
__device__ __forceinline__ void ldsm_x4t(uint32_t* r, uint32_t addr) {
    asm volatile("ldmatrix.sync.aligned.m8n8.x4.trans.shared.b16 {%0,%1,%2,%3}, [%4];"
        : "=r"(r[0]), "=r"(r[1]), "=r"(r[2]), "=r"(r[3]) : "r"(addr));
}
__device__ __forceinline__ void mma16816(float* c, const uint32_t* a,
                                         uint32_t b0, uint32_t b1) {
    asm volatile(
        "mma.sync.aligned.m16n8k16.row.col.f32.bf16.bf16.f32 "
        "{%0,%1,%2,%3}, {%4,%5,%6,%7}, {%8,%9}, {%0,%1,%2,%3};"
        : "+f"(c[0]), "+f"(c[1]), "+f"(c[2]), "+f"(c[3])
        : "r"(a[0]), "r"(a[1]), "r"(a[2]), "r"(a[3]), "r"(b0), "r"(b1));
}

// ============================ prep kernels =================================
// fused transpose of all scalar-path weights
__global__ __launch_bounds__(256) void tpose_all(
        const float* __restrict__ e3, const float* __restrict__ er1a,
        const float* __restrict__ er2a, const float* __restrict__ e2,
        const float* __restrict__ dt1, const float* __restrict__ b1,
        const float* __restrict__ b2, const float* __restrict__ b3,
        const float* __restrict__ b4, float* __restrict__ dst) {
    int i = blockIdx.x * 256 + threadIdx.x;
    if (i < 442368) {                       // 3 encoder conv3x3, ock K=9
        int layer = i / 147456, rem = i - layer * 147456;
        const float* s = layer == 0 ? e3 : (layer == 1 ? er1a : er2a);
        int co = rem / 1152, r = rem - co * 1152;
        dst[W3_OFF(layer) + r * 128 + co] = s[rem];
    } else if (i < 704512) {                // e2 ock K=16
        int j = i - 442368;
        int co = j / 2048, r = j - co * 2048;
        dst[WE2_OFF + r * 128 + co] = e2[j];
    } else if (i < 966656) {                // dt1 iok K=16
        int j = i - 704512;
        int ci = j / 2048, r = j - ci * 2048;
        int co = r / 16, k = r - co * 16;
        dst[WDT1_OFF + (ci * 16 + k) * 128 + co] = dt1[j];
    } else {                                // 4 conv1x1 ock K=1
        int j = i - 966656;
        int layer = j >> 14, rem = j & 16383;
        const float* s = layer == 0 ? b1 : (layer == 1 ? b2 : (layer == 2 ? b3 : b4));
        int co = rem >> 7, ci = rem & 127;
        dst[W1_OFF(layer) + ci * 128 + co] = s[rem];
    }
}

// mma weight prep: [co][ci][tap] fp32 -> per (layer,tap): rows = ci (k-major),
// 256B/row of co values, chunk-xor by (ci&7); bf16 hi plane (32KB) then lo (32KB)
__global__ __launch_bounds__(256) void wprep3(const float* __restrict__ w0,
                                              const float* __restrict__ w1,
                                              const float* __restrict__ w2) {
    int i = blockIdx.x * 256 + threadIdx.x;          // 442368 total
    int layer = i / 147456, rem = i - layer * 147456;
    const float* s = layer == 0 ? w0 : (layer == 1 ? w1 : w2);
    int tap = rem / 16384, rc = rem & 16383;
    int co = rc >> 7, ci = rc & 127;
    float v = s[(co * 128 + ci) * 9 + tap];
    __nv_bfloat16 hi = __float2bfloat16(v);
    __nv_bfloat16 lo = __float2bfloat16(v - __bfloat162float(hi));
    // row = ci, col = co; 16B chunk index (co>>3) xored with (row&7)
    uint32_t off = (uint32_t)ci * 256 + ((((uint32_t)co >> 3) ^ ((uint32_t)ci & 7)) * 16)
                 + ((uint32_t)co & 7) * 2;
    char* base = (char*)g_WT + (size_t)(layer * 9 + tap) * 65536;
    *(__nv_bfloat16*)(base + off) = hi;
    *(__nv_bfloat16*)(base + 32768 + off) = lo;
}

// NCHW fp32 -> NHWC bf16 hi/lo (optional ReLU)
__global__ __launch_bounds__(256) void cvt_nhwc(const float* __restrict__ src,
                                                __nv_bfloat16* __restrict__ hi,
                                                __nv_bfloat16* __restrict__ lo,
                                                int relu) {
    __shared__ __nv_bfloat16 sh[32][66], sl[32][66];
    const int p0 = blockIdx.x * 64, c0 = blockIdx.y * 32, b = blockIdx.z;
    const int t = threadIdx.x;
    #pragma unroll
    for (int it = 0; it < 8; it++) {
        int idx = t + it * 256;
        int c = idx >> 6, p = idx & 63;
        float v = src[((b * 128 + c0 + c) * 4096) + p0 + p];
        if (relu) v = fmaxf(v, 0.f);
        __nv_bfloat16 h = __float2bfloat16(v);
        sh[c][p] = h;
        sl[c][p] = __float2bfloat16(v - __bfloat162float(h));
    }
    __syncthreads();
    #pragma unroll
    for (int it = 0; it < 8; it++) {
        int idx = t + it * 256;
        int c = idx & 31, p = idx >> 5;
        size_t d = ((size_t)(b * 4096 + p0 + p) * 128) + c0 + c;
        hi[d] = sh[c][p];
        lo[d] = sl[c][p];
    }
}

// ---------------------------------------------------------------------------
// conv3x3 via mma.sync bf16 (decoder): block = 128 pixels (2 rows) x 128 co.
// 8 warps in 4(M) x 2(N): warp tile 32 x 64. 9 taps x 3 hi/lo passes, K=128.
// smem: Ahi 32K | Alo 32K | W hi/lo 64K | bias 512B
// W smem rows = ci (k), cols = co; B fragments via ldmatrix.x4.trans with
// lane rows = k (wrow), chunk = co octet.
// ---------------------------------------------------------------------------
__global__ __launch_bounds__(256) void conv3x3_mma(
        const __nv_bfloat16* __restrict__ hi,
        const __nv_bfloat16* __restrict__ lo,
        const uint4* __restrict__ wt,     // layer base: 9 taps x 4096 uint4
        const float* __restrict__ bias,
        float* __restrict__ out) {
    extern __shared__ char smem[];
    const uint32_t sbase = smem_u32(smem);
    const int tid = threadIdx.x;
    const int lane = tid & 31, warp = tid >> 5;
    const int b = blockIdx.x >> 5;
    const int y0 = (blockIdx.x & 31) * 2;
    const int mtile = (warp & 3) * 32;
    const int ntile = (warp >> 2) * 64;
    float* sb = (float*)(smem + 131072);
    if (tid < 128) sb[tid] = bias[tid];

    float acc[2][8][4];
    #pragma unroll
    for (int mi = 0; mi < 2; mi++)
        #pragma unroll
        for (int j = 0; j < 8; j++)
            #pragma unroll
            for (int q = 0; q < 4; q++) acc[mi][j][q] = 0.f;

    const int px = tid >> 1, half = tid & 1;
    const uint32_t rA = (uint32_t)(mtile + (lane & 15));
    const uint32_t cl = (uint32_t)(lane >> 4);
    const uint32_t swz = (uint32_t)(lane & 7);
    // B addressing: lane row = k within the 16-k step; octet = co chunk
    const uint32_t wrow = (uint32_t)((lane & 7) + ((lane >> 4) << 3));  // 0..15
    const uint32_t wq   = (uint32_t)((ntile >> 3) + ((lane >> 3) & 1));

    #pragma unroll 1
    for (int tap = 0; tap < 9; tap++) {
        const int dy = tap / 3 - 1, dx = tap % 3 - 1;
        __syncthreads();   // previous tap's ldmatrix reads done before overwrite
        // ---- stage A (shifted activations), both planes, chunk-xor swizzle ----
        {
            const int yy = y0 + (px >> 6) + dy;
            const int xx = (px & 63) + dx;
            const bool valid = ((unsigned)yy < 64u) && ((unsigned)xx < 64u);
            const size_t rowoff = valid ? ((size_t)((b << 12) + yy * 64 + xx) * 128) : 0;
            const uint4* qh = (const uint4*)(hi + rowoff);
            const uint4* ql = (const uint4*)(lo + rowoff);
            uint4* AH = (uint4*)smem;
            uint4* AL = (uint4*)(smem + 32768);
            const uint4 z = make_uint4(0, 0, 0, 0);
            #pragma unroll
            for (int j = 0; j < 8; j++) {
                int cidx = half * 8 + j;
                int si = px * 16 + (cidx ^ (px & 7));
                AH[si] = valid ? qh[cidx] : z;
                AL[si] = valid ? ql[cidx] : z;
            }
        }
        // ---- stage W (this tap, hi|lo 64KB, already swizzled in gmem) ----
        {
            const uint4* wsrc = wt + (size_t)tap * 4096;
            uint4* WD = (uint4*)(smem + 65536);
            #pragma unroll
            for (int i = 0; i < 16; i++) WD[tid + i * 256] = wsrc[tid + i * 256];
        }
        __syncthreads();
        // ---- 3 passes: Ahi*Whi, Ahi*Wlo, Alo*Whi ----
        #pragma unroll 1
        for (int pass = 0; pass < 3; pass++) {
            const uint32_t Ab = sbase + (pass < 2 ? 0u : 32768u) + rA * 256u;
            const uint32_t Wb = sbase + 65536u + (pass == 1 ? 32768u : 0u);
            #pragma unroll
            for (int ks = 0; ks < 8; ks++) {
                const uint32_t ch = (((uint32_t)(2 * ks) + cl) ^ swz) * 16u;
                uint32_t a0[4], a1[4];
                ldsm_x4(a0, Ab + ch);
                ldsm_x4(a1, Ab + 4096u + ch);
                const uint32_t WbRow = Wb + ((uint32_t)ks * 16u + wrow) * 256u;
                uint32_t bf0[4], bf1[4], bf2[4], bf3[4];
                ldsm_x4t(bf0, WbRow + (((wq + 0u) ^ swz) * 16u));
                ldsm_x4t(bf1, WbRow + (((wq + 2u) ^ swz) * 16u));
                ldsm_x4t(bf2, WbRow + (((wq + 4u) ^ swz) * 16u));
                ldsm_x4t(bf3, WbRow + (((wq + 6u) ^ swz) * 16u));
                #pragma unroll
                for (int j = 0; j < 8; j++) {
                    const uint32_t* f = (j >> 1) == 0 ? bf0 : ((j >> 1) == 1 ? bf1 : ((j >> 1) == 2 ? bf2 : bf3));
                    uint32_t b0 = (j & 1) ? f[1] : f[0];
                    uint32_t b1 = (j & 1) ? f[3] : f[2];
                    mma16816(acc[0][j], a0, b0, b1);
                    mma16816(acc[1][j], a1, b0, b1);
                }
            }
        }
    }

    // ---- epilogue: acc (m=pixel, n=co) + bias -> NCHW fp32 ----
    const int m_r = lane >> 2, n_c = (lane & 3) * 2;
    const int sp0 = y0 * 64;
    #pragma unroll
    for (int mi = 0; mi < 2; mi++) {
        #pragma unroll
        for (int j = 0; j < 8; j++) {
            int m = mtile + mi * 16 + m_r;
            int n = ntile + j * 8 + n_c;
            float* o0 = out + ((size_t)(b * 128 + n) << 12) + sp0 + m;
            float* o1 = o0 + 4096;          // co n+1
            o0[0] = acc[mi][j][0] + sb[n];
            o1[0] = acc[mi][j][1] + sb[n + 1];
            o0[8] = acc[mi][j][2] + sb[n];       // m+8 same co
            o1[8] = acc[mi][j][3] + sb[n + 1];
        }
    }
}

// ---------------------------------------------------------------------------
// e1: conv 3->128, k4 s2 p1, 256x256 -> 128x128, ReLU
// ---------------------------------------------------------------------------
__global__ __launch_bounds__(256) void e1_k(const float* __restrict__ x,
                                            const float* __restrict__ w,
                                            const float* __restrict__ bias,
                                            float* __restrict__ out) {
    __shared__ float ws[128*3*16];
    for (int i = threadIdx.x; i < 128*3*16; i += 256) ws[i] = w[i];
    __syncthreads();
    int g = blockIdx.x * 256 + threadIdx.x;
    int ox = g & 127, oy = (g >> 7) & 127, co = (g >> 14) & 127, b = g >> 21;
    float acc = bias[co];
    int iy0 = 2*oy - 1, ix0 = 2*ox - 1;
    #pragma unroll
    for (int ci = 0; ci < 3; ci++) {
        const float* xp = x + (b*3 + ci) * 65536;
        const float* wp = ws + (co*3 + ci) * 16;
        #pragma unroll
        for (int ky = 0; ky < 4; ky++) {
            int iy = iy0 + ky;
            if ((unsigned)iy < 256u) {
                #pragma unroll
                for (int kx = 0; kx < 4; kx++) {
                    int ix = ix0 + kx;
                    if ((unsigned)ix < 256u)
                        acc = fmaf(xp[iy*256 + ix], wp[ky*4 + kx], acc);
                }
            }
        }
    }
    out[g] = fmaxf(acc, 0.f);
}

// ---------------------------------------------------------------------------
// e2: conv 128->128, k4 s2 p1, 128x128 -> 64x64, ReLU
// ---------------------------------------------------------------------------
__global__ __launch_bounds__(128) void conv4s2_k(const float* __restrict__ in,
                                                 const float* __restrict__ wT,
                                                 const float* __restrict__ bias,
                                                 float* __restrict__ out) {
    const int co = threadIdx.x;
    const int ox0 = blockIdx.x * 8, oy0 = blockIdx.y * 8, b = blockIdx.z;
    __shared__ float s[8][18][20];
    float acc[64];
    {
        float bv = bias[co];
        #pragma unroll
        for (int i = 0; i < 64; i++) acc[i] = bv;
    }
    const int iy0 = oy0*2 - 1, ix0 = ox0*2 - 1;
    for (int cc = 0; cc < 128; cc += 8) {
        __syncthreads();
        for (int idx = co; idx < 8*324; idx += 128) {
            int ci = idx / 324, rr = idx % 324, r = rr / 18, cl = rr % 18;
            int iy = iy0 + r, ix = ix0 + cl;
            float v = 0.f;
            if ((unsigned)iy < 128u && (unsigned)ix < 128u)
                v = in[((b*128 + cc + ci) * 128 + iy) * 128 + ix];
            s[ci][r][cl] = v;
        }
        __syncthreads();
        #pragma unroll 1
        for (int ci = 0; ci < 8; ci++) {
            float wt[16];
            const float* wp = wT + (cc + ci) * 16 * 128 + co;
            #pragma unroll
            for (int k = 0; k < 16; k++) wt[k] = wp[k*128];
            #pragma unroll
            for (int r = 0; r < 18; r++) {
                float4 f0 = *(const float4*)&s[ci][r][0];
                float4 f1 = *(const float4*)&s[ci][r][4];
                float4 f2 = *(const float4*)&s[ci][r][8];
                float4 f3 = *(const float4*)&s[ci][r][12];
                float4 f4 = *(const float4*)&s[ci][r][16];
                float row[18] = {f0.x,f0.y,f0.z,f0.w, f1.x,f1.y,f1.z,f1.w,
                                 f2.x,f2.y,f2.z,f2.w, f3.x,f3.y,f3.z,f3.w,
                                 f4.x,f4.y};
                #pragma unroll
                for (int ky = 0; ky < 4; ky++) {
                    if (((r - ky) & 1) == 0) {
                        int py = (r - ky) >> 1;
                        if (py >= 0 && py < 8) {
                            #pragma unroll
                            for (int px = 0; px < 8; px++) {
                                float a = acc[py*8 + px];
                                a = fmaf(row[2*px + 0], wt[ky*4 + 0], a);
                                a = fmaf(row[2*px + 1], wt[ky*4 + 1], a);
                                a = fmaf(row[2*px + 2], wt[ky*4 + 2], a);
                                a = fmaf(row[2*px + 3], wt[ky*4 + 3], a);
                                acc[py*8 + px] = a;
                            }
                        }
                    }
                }
            }
        }
    }
    float* op = out + ((b*128 + co) * 64 + oy0) * 64 + ox0;
    #pragma unroll
    for (int py = 0; py < 8; py++)
        #pragma unroll
        for (int px = 0; px < 8; px++)
            op[py*64 + px] = fmaxf(acc[py*8 + px], 0.f);
}

// ---------------------------------------------------------------------------
// conv3x3 scalar (encoder), bit-identical
// ---------------------------------------------------------------------------
template<bool RELU_IN>
__global__ __launch_bounds__(128) void conv3x3_k(const float* __restrict__ in,
                                                 const float* __restrict__ wT,
                                                 const float* __restrict__ bias,
                                                 float* __restrict__ out) {
    const int co = threadIdx.x;
    const int ox0 = blockIdx.x * 8, oy0 = blockIdx.y * 8, b = blockIdx.z;
    __shared__ float s[16][10][12];
    float acc[64];
    {
        float bv = bias[co];
        #pragma unroll
        for (int i = 0; i < 64; i++) acc[i] = bv;
    }
    for (int cc = 0; cc < 128; cc += 16) {
        __syncthreads();
        for (int idx = co; idx < 16*100; idx += 128) {
            int ci = idx / 100, rr = idx % 100, r = rr / 10, cl = rr % 10;
            int iy = oy0 - 1 + r, ix = ox0 - 1 + cl;
            float v = 0.f;
            if ((unsigned)iy < 64u && (unsigned)ix < 64u) {
                v = in[((b*128 + cc + ci) * 64 + iy) * 64 + ix];
                if (RELU_IN) v = fmaxf(v, 0.f);
            }
            s[ci][r][cl] = v;
        }
        __syncthreads();
        #pragma unroll 1
        for (int ci = 0; ci < 16; ci++) {
            float wt[9];
            const float* wp = wT + (cc + ci) * 9 * 128 + co;
            #pragma unroll
            for (int k = 0; k < 9; k++) wt[k] = wp[k*128];
            #pragma unroll
            for (int r = 0; r < 10; r++) {
                float4 f0 = *(const float4*)&s[ci][r][0];
                float4 f1 = *(const float4*)&s[ci][r][4];
                float4 f2 = *(const float4*)&s[ci][r][8];
                float row[10] = {f0.x,f0.y,f0.z,f0.w, f1.x,f1.y,f1.z,f1.w,
                                 f2.x,f2.y};
                #pragma unroll
                for (int ky = 0; ky < 3; ky++) {
                    int py = r - ky;
                    if (py >= 0 && py < 8) {
                        #pragma unroll
                        for (int px = 0; px < 8; px++) {
                            float a = acc[py*8 + px];
                            a = fmaf(row[px + 0], wt[ky*3 + 0], a);
                            a = fmaf(row[px + 1], wt[ky*3 + 1], a);
                            a = fmaf(row[px + 2], wt[ky*3 + 2], a);
                            acc[py*8 + px] = a;
                        }
                    }
                }
            }
        }
    }
    float* op = out + ((b*128 + co) * 64 + oy0) * 64 + ox0;
    #pragma unroll
    for (int py = 0; py < 8; py++)
        #pragma unroll
        for (int px = 0; px < 8; px++)
            op[py*64 + px] = acc[py*8 + px];
}

// ---------------------------------------------------------------------------
// conv1x1 + input ReLU + residual
// ---------------------------------------------------------------------------
__global__ __launch_bounds__(128) void conv1x1_res_k(const float* __restrict__ in,
                                                     const float* __restrict__ wT,
                                                     const float* __restrict__ bias,
                                                     const float* __restrict__ res,
                                                     float* __restrict__ out) {
    const int co = threadIdx.x;
    const int b = blockIdx.x >> 6;
    const int p0 = (blockIdx.x & 63) * 64;
    __shared__ float s[32][64];
    float acc[64];
    {
        float bv = bias[co];
        #pragma unroll
        for (int i = 0; i < 64; i++) acc[i] = bv;
    }
    for (int cc = 0; cc < 128; cc += 32) {
        __syncthreads();
        for (int idx = co; idx < 32*64; idx += 128) {
            int ci = idx >> 6, p = idx & 63;
            float v = in[(b*128 + cc + ci) * 4096 + p0 + p];
            s[ci][p] = fmaxf(v, 0.f);
        }
        __syncthreads();
        #pragma unroll 1
        for (int ci = 0; ci < 32; ci++) {
            float wv = wT[(cc + ci) * 128 + co];
            const float4* sp = (const float4*)s[ci];
            #pragma unroll
            for (int p4 = 0; p4 < 16; p4++) {
                float4 v = sp[p4];
                acc[4*p4 + 0] = fmaf(v.x, wv, acc[4*p4 + 0]);
                acc[4*p4 + 1] = fmaf(v.y, wv, acc[4*p4 + 1]);
                acc[4*p4 + 2] = fmaf(v.z, wv, acc[4*p4 + 2]);
                acc[4*p4 + 3] = fmaf(v.w, wv, acc[4*p4 + 3]);
            }
        }
    }
    const float* rp = res + (b*128 + co) * 4096 + p0;
    float* op = out + (b*128 + co) * 4096 + p0;
    #pragma unroll
    for (int p = 0; p < 64; p++) op[p] = rp[p] + acc[p];
}

// ---------------------------------------------------------------------------
// VQ (reference-numerics replica) — unchanged
// ---------------------------------------------------------------------------
__global__ __launch_bounds__(256) void vq_k(const float* __restrict__ ze,
                                            const float* __restrict__ cb,
                                            float* __restrict__ zq) {
    const int b = blockIdx.x >> 6;
    const int p0 = (blockIdx.x & 63) * 64;
    __shared__ float zs[128][64];
    __shared__ float cs[16][128];
    __shared__ float zzs[64];
    __shared__ float ees[512];
    __shared__ float rb1[256]; __shared__ int ri1[256];
    __shared__ int   finalidx[64];
    const int t = threadIdx.x;
    const float* zb = ze + b * 128 * 4096 + p0;
    for (int idx = t; idx < 128*64; idx += 256) {
        int c = idx >> 6, p = idx & 63;
        zs[c][p] = zb[c*4096 + p];
    }
    for (int k = t; k < 512; k += 256) {
        const float* cp = cb + k * 128;
        double acc = 0.0;
        for (int c = 0; c < 128; c++) { double e = (double)cp[c]; acc += e * e; }
        ees[k] = (float)acc;
    }
    __syncthreads();
    if (t < 64) {
        double acc = 0.0;
        for (int c = 0; c < 128; c++) { double z = (double)zs[c][t]; acc += z * z; }
        zzs[t] = (float)acc;
    }
    __syncthreads();

    float b1 = 3.4e38f; int i1 = 0x7fffffff;
    const int pos = t & 63, cg = t >> 6;
    const float zz = zzs[pos];
    for (int k0 = 0; k0 < 512; k0 += 16) {
        __syncthreads();
        for (int idx = t; idx < 16*128; idx += 256)
            cs[idx >> 7][idx & 127] = cb[k0*128 + idx];
        __syncthreads();
        float dot0 = 0.f, dot1 = 0.f, dot2 = 0.f, dot3 = 0.f;
        const float4* e0 = (const float4*)cs[cg + 0];
        const float4* e1 = (const float4*)cs[cg + 4];
        const float4* e2 = (const float4*)cs[cg + 8];
        const float4* e3 = (const float4*)cs[cg + 12];
        #pragma unroll 4
        for (int c4 = 0; c4 < 32; c4++) {
            float z0 = zs[4*c4 + 0][pos];
            float z1 = zs[4*c4 + 1][pos];
            float z2 = zs[4*c4 + 2][pos];
            float z3 = zs[4*c4 + 3][pos];
            float4 a = e0[c4], bb = e1[c4], cA = e2[c4], dd = e3[c4];
            dot0 = __fmaf_rn(z0, a.x, dot0);  dot0 = __fmaf_rn(z1, a.y, dot0);
            dot0 = __fmaf_rn(z2, a.z, dot0);  dot0 = __fmaf_rn(z3, a.w, dot0);
            dot1 = __fmaf_rn(z0, bb.x, dot1); dot1 = __fmaf_rn(z1, bb.y, dot1);
            dot1 = __fmaf_rn(z2, bb.z, dot1); dot1 = __fmaf_rn(z3, bb.w, dot1);
            dot2 = __fmaf_rn(z0, cA.x, dot2); dot2 = __fmaf_rn(z1, cA.y, dot2);
            dot2 = __fmaf_rn(z2, cA.z, dot2); dot2 = __fmaf_rn(z3, cA.w, dot2);
            dot3 = __fmaf_rn(z0, dd.x, dot3); dot3 = __fmaf_rn(z1, dd.y, dot3);
            dot3 = __fmaf_rn(z2, dd.z, dot3); dot3 = __fmaf_rn(z3, dd.w, dot3);
        }
        float dts[4] = {dot0, dot1, dot2, dot3};
        #pragma unroll
        for (int m = 0; m < 4; m++) {
            int gidx = k0 + cg + 4*m;
            float d = __fadd_rn(__fsub_rn(zz, __fmul_rn(2.f, dts[m])), ees[gidx]);
            if (d < b1) { b1 = d; i1 = gidx; }
        }
    }
    rb1[t] = b1; ri1[t] = i1;
    __syncthreads();
    if (t < 64) {
        float B1 = rb1[t]; int I1 = ri1[t];
        #pragma unroll
        for (int g = 1; g < 4; g++) {
            float v = rb1[t + 64*g]; int vi = ri1[t + 64*g];
            if (v < B1 || (v == B1 && vi < I1)) { B1 = v; I1 = vi; }
        }
        finalidx[t] = I1;
    }
    __syncthreads();
    float* zqb = zq + b * 128 * 4096 + p0;
    for (int idx = t; idx < 128*64; idx += 256) {
        int c = idx >> 6, p = idx & 63;
        zqb[c*4096 + p] = cb[finalidx[p]*128 + c];
    }
}

// ---------------------------------------------------------------------------
// dt1: ConvTranspose2d 128->128, k4 s2 p1, 64x64 -> 128x128, ReLU
// ---------------------------------------------------------------------------
__global__ __launch_bounds__(128) void dt1_k(const float* __restrict__ in,
                                             const float* __restrict__ wT,
                                             const float* __restrict__ bias,
                                             float* __restrict__ out) {
    const int co = threadIdx.x;
    const int tx = blockIdx.x, ty = blockIdx.y, b = blockIdx.z;
    const int ox0 = tx * 8, oy0 = ty * 8;
    const int iyb = 4*ty - 1, ixb = 4*tx - 1;
    __shared__ float s[16][6][8];
    float acc[64];
    {
        float bv = bias[co];
        #pragma unroll
        for (int i = 0; i < 64; i++) acc[i] = bv;
    }
    for (int cc = 0; cc < 128; cc += 16) {
        __syncthreads();
        for (int idx = co; idx < 16*36; idx += 128) {
            int ci = idx / 36, rr = idx % 36, r = rr / 6, cl = rr % 6;
            int iy = iyb + r, ix = ixb + cl;
            float v = 0.f;
            if ((unsigned)iy < 64u && (unsigned)ix < 64u)
                v = in[((b*128 + cc + ci) << 12) + iy*64 + ix];
            s[ci][r][cl] = v;
        }
        __syncthreads();
        #pragma unroll 1
        for (int ci = 0; ci < 16; ci++) {
            float wt[16];
            const float* wp = wT + (cc + ci) * 16 * 128 + co;
            #pragma unroll
            for (int k = 0; k < 16; k++) wt[k] = wp[k*128];
            #pragma unroll
            for (int py = 0; py < 8; py++) {
                const int ky0 = 1 - (py & 1);
                const int q = (py + 1 - ky0) >> 1;
                float4 h0 = *(const float4*)&s[ci][q+1][0];
                float4 h1 = *(const float4*)&s[ci][q+1][4];
                float4 l0 = *(const float4*)&s[ci][q][0];
                float4 l1 = *(const float4*)&s[ci][q][4];
                float rH[6] = {h0.x, h0.y, h0.z, h0.w, h1.x, h1.y};
                float rL[6] = {l0.x, l0.y, l0.z, l0.w, l1.x, l1.y};
                #pragma unroll
                for (int px = 0; px < 8; px++) {
                    const int kx0 = 1 - (px & 1);
                    const int qx = (px + 1 - kx0) >> 1;
                    float a = acc[py*8 + px];
                    a = fmaf(rH[qx+1], wt[ky0*4 + kx0],           a);
                    a = fmaf(rH[qx],   wt[ky0*4 + kx0 + 2],       a);
                    a = fmaf(rL[qx+1], wt[(ky0+2)*4 + kx0],       a);
                    a = fmaf(rL[qx],   wt[(ky0+2)*4 + kx0 + 2],   a);
                    acc[py*8 + px] = a;
                }
            }
        }
    }
    float* op = out + ((b*128 + co) << 14) + oy0*128 + ox0;
    #pragma unroll
    for (int py = 0; py < 8; py++)
        #pragma unroll
        for (int px = 0; px < 8; px++)
            op[py*128 + px] = fmaxf(acc[py*8 + px], 0.f);
}

// ---------------------------------------------------------------------------
// dt2: ConvTranspose2d 128->3, k4 s2 p1, 128x128 -> 256x256
// ---------------------------------------------------------------------------
__global__ __launch_bounds__(256) void dt2_k(const float* __restrict__ in,
                                             const float* __restrict__ w,
                                             const float* __restrict__ bias,
                                             float* __restrict__ out) {
    __shared__ float ws[128*3*16];
    for (int i = threadIdx.x; i < 128*3*16; i += 256) ws[i] = w[i];
    __syncthreads();
    int g = blockIdx.x * 256 + threadIdx.x;
    int ox = g & 255, oy = (g >> 8) & 255, b = g >> 16;
    float a0 = bias[0], a1 = bias[1], a2 = bias[2];
    const int ky0 = (oy + 1) & 1, kx0 = (ox + 1) & 1;
    const int iyh = (oy + 1 - ky0) >> 1, ixh = (ox + 1 - kx0) >> 1;
    #pragma unroll 4
    for (int ci = 0; ci < 128; ci++) {
        const float* ip = in + ((b*128 + ci) << 14);
        const float* wp = ws + ci * 48;
        #pragma unroll
        for (int dy = 0; dy < 2; dy++) {
            int iy = iyh - dy, ky = ky0 + 2*dy;
            if ((unsigned)iy < 128u) {
                #pragma unroll
                for (int dx = 0; dx < 2; dx++) {
                    int ix = ixh - dx, kx = kx0 + 2*dx;
                    if ((unsigned)ix < 128u) {
                        float v = ip[iy*128 + ix];
                        int wk = ky*4 + kx;
                        a0 = fmaf(v, wp[wk],      a0);
                        a1 = fmaf(v, wp[16 + wk], a1);
                        a2 = fmaf(v, wp[32 + wk], a2);
                    }
                }
            }
        }
    }
    int sp = oy*256 + ox;
    out[(b*3 + 0) * 65536 + sp] = a0;
    out[(b*3 + 1) * 65536 + sp] = a1;
    out[(b*3 + 2) * 65536 + sp] = a2;
}

// ---------------------------------------------------------------------------

extern "C" void kernel_launch(void* const* d_in, const int* in_sizes, int n_in,
                              void* d_out, int out_size) {
    const float* x      = (const float*)d_in[0];
    const float* e1_w   = (const float*)d_in[1];  const float* e1_b = (const float*)d_in[2];
    const float* e2_w   = (const float*)d_in[3];  const float* e2_b = (const float*)d_in[4];
    const float* e3_w   = (const float*)d_in[5];  const float* e3_b = (const float*)d_in[6];
    const float* er1a_w = (const float*)d_in[7];  const float* er1a_b = (const float*)d_in[8];
    const float* er1b_w = (const float*)d_in[9];  const float* er1b_b = (const float*)d_in[10];
    const float* er2a_w = (const float*)d_in[11]; const float* er2a_b = (const float*)d_in[12];
    const float* er2b_w = (const float*)d_in[13]; const float* er2b_b = (const float*)d_in[14];
    const float* codebook = (const float*)d_in[15];
    const float* d1_w   = (const float*)d_in[16]; const float* d1_b = (const float*)d_in[17];
    const float* dr1a_w = (const float*)d_in[18]; const float* dr1a_b = (const float*)d_in[19];
    const float* dr1b_w = (const float*)d_in[20]; const float* dr1b_b = (const float*)d_in[21];
    const float* dr2a_w = (const float*)d_in[22]; const float* dr2a_b = (const float*)d_in[23];
    const float* dr2b_w = (const float*)d_in[24]; const float* dr2b_b = (const float*)d_in[25];
    const float* dt1_w  = (const float*)d_in[26]; const float* dt1_b = (const float*)d_in[27];
    const float* dt2_w  = (const float*)d_in[28]; const float* dt2_b = (const float*)d_in[29];

    float* out   = (float*)d_out;
    float* xhat  = out;
    float* ze    = out + XHAT_ELEMS;
    float* zq    = out + XHAT_ELEMS + ZE_ELEMS;

    float* A;  cudaGetSymbolAddress((void**)&A,  g_A);
    float* Bf; cudaGetSymbolAddress((void**)&Bf, g_B);
    float* Cf; cudaGetSymbolAddress((void**)&Cf, g_C);
    float* Df; cudaGetSymbolAddress((void**)&Df, g_D);
    float* Tf; cudaGetSymbolAddress((void**)&Tf, g_T);
    float* W;  cudaGetSymbolAddress((void**)&W,  g_W);
    __nv_bfloat16* Hi; cudaGetSymbolAddress((void**)&Hi, g_Hi);
    __nv_bfloat16* Lo; cudaGetSymbolAddress((void**)&Lo, g_Lo);
    uint4* WT; cudaGetSymbolAddress((void**)&WT, g_WT);

    cudaFuncSetAttribute(conv3x3_mma, cudaFuncAttributeMaxDynamicSharedMemorySize, 131584);

    // weight prep
    tpose_all<<<4032, 256>>>(e3_w, er1a_w, er2a_w, e2_w, dt1_w,
                             er1b_w, er2b_w, dr1b_w, dr2b_w, W);
    wprep3<<<1728, 256>>>(d1_w, dr1a_w, dr2a_w);

    dim3 tile64(8, 8, BATCH);
    dim3 tile128(16, 16, BATCH);
    dim3 cvtg(64, 4, 16);

    // encoder (scalar, bit-identical)
    e1_k<<<(16*128*128*128)/256, 256>>>(x, e1_w, e1_b, A);
    conv4s2_k<<<tile64, 128>>>(A, W + WE2_OFF, e2_b, Bf);
    conv3x3_k<false><<<tile64, 128>>>(Bf, W + W3_OFF(0), e3_b, Cf);
    conv3x3_k<true><<<tile64, 128>>>(Cf, W + W3_OFF(1), er1a_b, Tf);
    conv1x1_res_k<<<16*64, 128>>>(Tf, W + W1_OFF(0), er1b_b, Cf, Df);
    conv3x3_k<true><<<tile64, 128>>>(Df, W + W3_OFF(2), er2a_b, Tf);
    conv1x1_res_k<<<16*64, 128>>>(Tf, W + W1_OFF(1), er2b_b, Df, ze);
    // VQ
    vq_k<<<16*64, 256>>>(ze, codebook, zq);
    // decoder: 3x3 convs on mma.sync tensor cores
    cvt_nhwc<<<cvtg, 256>>>(zq, Hi, Lo, 0);
    conv3x3_mma<<<512, 256, 131584>>>(Hi, Lo, WT + (size_t)0*9*4096, d1_b, Cf);
    cvt_nhwc<<<cvtg, 256>>>(Cf, Hi, Lo, 1);
    conv3x3_mma<<<512, 256, 131584>>>(Hi, Lo, WT + (size_t)1*9*4096, dr1a_b, Tf);
    conv1x1_res_k<<<16*64, 128>>>(Tf, W + W1_OFF(2), dr1b_b, Cf, Df);
    cvt_nhwc<<<cvtg, 256>>>(Df, Hi, Lo, 1);
    conv3x3_mma<<<512, 256, 131584>>>(Hi, Lo, WT + (size_t)2*9*4096, dr2a_b, Tf);
    conv1x1_res_k<<<16*64, 128>>>(Tf, W + W1_OFF(3), dr2b_b, Df, Bf);
    dt1_k<<<tile128, 128>>>(Bf, W + WDT1_OFF, dt1_b, A);
    dt2_k<<<(16*256*256)/256, 256>>>(A, dt2_w, dt2_b, xhat);
}

// round 14
// speedup vs baseline: 1.9249x; 1.0869x over previous
#include <cuda_runtime.h>
#include <cuda_bf16.h>
#include <cstdint>

// ---------------------------------------------------------------------------
// VQ-VAE forward. Encoder: fp32 scalar (bit-stable for VQ). Decoder 3x3 convs
// AND dt1 (ConvTranspose 4x4 s2, via 4 parity classes): warp mma.sync bf16
// hi/lo split (3-pass). d_out: x_hat | ze | zq
// ---------------------------------------------------------------------------

#define BATCH 16
#define XHAT_ELEMS (16*3*256*256)
#define ZE_ELEMS   (16*128*64*64)

__device__ float g_A[16*128*128*128];
__device__ float g_B[ZE_ELEMS];
__device__ float g_C[ZE_ELEMS];
__device__ float g_D[ZE_ELEMS];
__device__ float g_T[ZE_ELEMS];
__device__ float g_W[1474560];             // scalar transposed weights
__device__ __nv_bfloat16 g_Hi[ZE_ELEMS];   // NHWC hi plane
__device__ __nv_bfloat16 g_Lo[ZE_ELEMS];   // NHWC lo plane
// mma weights: 3 conv3x3 layers x 9 taps + dt1 4 parity x 4 taps; 64KB each
__device__ uint4 g_WT[(3*9 + 16) * 4096];
#define WT_DT1_BASE (27 * 4096)

#define W3_OFF(i)  ((i) * 147456)
#define WE2_OFF    884736
#define WDT1_OFF   1146880
#define W1_OFF(i)  (1409024 + (i) * 16384)

// ============================ mma helpers ==================================
__device__ __forceinline__ uint32_t smem_u32(const void* p) {
    uint32_t a;
    asm("{ .reg .u64 t; cvta.to.shared.u64 t, %1; cvt.u32.u64 %0, t; }" : "=r"(a) : "l"(p));
    return a;
}
__device__ __forceinline__ void ldsm_x4(uint32_t* r, uint32_t addr) {
    asm volatile("ldmatrix.sync.aligned.m8n8.x4.shared.b16 {%0,%1,%2,%3}, [%4];"
        : "=r"(r[0]), "=r"(r[1]), "=r"(r[2]), "=r"(r[3]) : "r"(addr));
}
__device__ __forceinline__ void ldsm_x4t(uint32_t* r, uint32_t addr) {
    asm volatile("ldmatrix.sync.aligned.m8n8.x4.trans.shared.b16 {%0,%1,%2,%3}, [%4];"
        : "=r"(r[0]), "=r"(r[1]), "=r"(r[2]), "=r"(r[3]) : "r"(addr));
}
__device__ __forceinline__ void mma16816(float* c, const uint32_t* a,
                                         uint32_t b0, uint32_t b1) {
    asm volatile(
        "mma.sync.aligned.m16n8k16.row.col.f32.bf16.bf16.f32 "
        "{%0,%1,%2,%3}, {%4,%5,%6,%7}, {%8,%9}, {%0,%1,%2,%3};"
        : "+f"(c[0]), "+f"(c[1]), "+f"(c[2]), "+f"(c[3])
        : "r"(a[0]), "r"(a[1]), "r"(a[2]), "r"(a[3]), "r"(b0), "r"(b1));
}

// ============================ prep kernels =================================
__global__ __launch_bounds__(256) void tpose_all(
        const float* __restrict__ e3, const float* __restrict__ er1a,
        const float* __restrict__ er2a, const float* __restrict__ e2,
        const float* __restrict__ dt1, const float* __restrict__ b1,
        const float* __restrict__ b2, const float* __restrict__ b3,
        const float* __restrict__ b4, float* __restrict__ dst) {
    int i = blockIdx.x * 256 + threadIdx.x;
    if (i < 442368) {
        int layer = i / 147456, rem = i - layer * 147456;
        const float* s = layer == 0 ? e3 : (layer == 1 ? er1a : er2a);
        int co = rem / 1152, r = rem - co * 1152;
        dst[W3_OFF(layer) + r * 128 + co] = s[rem];
    } else if (i < 704512) {
        int j = i - 442368;
        int co = j / 2048, r = j - co * 2048;
        dst[WE2_OFF + r * 128 + co] = e2[j];
    } else if (i < 966656) {
        int j = i - 704512;
        int ci = j / 2048, r = j - ci * 2048;
        int co = r / 16, k = r - co * 16;
        dst[WDT1_OFF + (ci * 16 + k) * 128 + co] = dt1[j];
    } else {
        int j = i - 966656;
        int layer = j >> 14, rem = j & 16383;
        const float* s = layer == 0 ? b1 : (layer == 1 ? b2 : (layer == 2 ? b3 : b4));
        int co = rem >> 7, ci = rem & 127;
        dst[W1_OFF(layer) + ci * 128 + co] = s[rem];
    }
}

// conv3x3 mma weights: rows = ci (k-major), cols = co, chunk-xor by (ci&7)
__global__ __launch_bounds__(256) void wprep3(const float* __restrict__ w0,
                                              const float* __restrict__ w1,
                                              const float* __restrict__ w2) {
    int i = blockIdx.x * 256 + threadIdx.x;          // 442368 total
    int layer = i / 147456, rem = i - layer * 147456;
    const float* s = layer == 0 ? w0 : (layer == 1 ? w1 : w2);
    int tap = rem / 16384, rc = rem & 16383;
    int co = rc >> 7, ci = rc & 127;
    float v = s[(co * 128 + ci) * 9 + tap];
    __nv_bfloat16 hi = __float2bfloat16(v);
    __nv_bfloat16 lo = __float2bfloat16(v - __bfloat162float(hi));
    uint32_t off = (uint32_t)ci * 256 + ((((uint32_t)co >> 3) ^ ((uint32_t)ci & 7)) * 16)
                 + ((uint32_t)co & 7) * 2;
    char* base = (char*)g_WT + (size_t)(layer * 9 + tap) * 65536;
    *(__nv_bfloat16*)(base + off) = hi;
    *(__nv_bfloat16*)(base + 32768 + off) = lo;
}

// dt1 mma weights: scatter [ci][co][ky][kx] into (parity p, tap t) 64KB tiles.
// ky -> (sy,ty): 0->(1,1) 1->(0,0) 2->(1,0) 3->(0,1); same for kx.
__global__ __launch_bounds__(256) void wprep_dt1(const float* __restrict__ w) {
    int i = blockIdx.x * 256 + threadIdx.x;          // 262144 total
    int ci = i >> 11, rem = i & 2047;
    int co = rem >> 4, k = rem & 15;
    int ky = k >> 2, kx = k & 3;
    int sy = 1 - (ky & 1), ty = (ky == 0 || ky == 3) ? 1 : 0;
    int sx = 1 - (kx & 1), tx = (kx == 0 || kx == 3) ? 1 : 0;
    int p = sy * 2 + sx, t = ty * 2 + tx;
    float v = w[i];
    __nv_bfloat16 hi = __float2bfloat16(v);
    __nv_bfloat16 lo = __float2bfloat16(v - __bfloat162float(hi));
    uint32_t off = (uint32_t)ci * 256 + ((((uint32_t)co >> 3) ^ ((uint32_t)ci & 7)) * 16)
                 + ((uint32_t)co & 7) * 2;
    char* base = (char*)g_WT + (size_t)(WT_DT1_BASE + (p * 4 + t) * 4096) * 16;
    *(__nv_bfloat16*)(base + off) = hi;
    *(__nv_bfloat16*)(base + 32768 + off) = lo;
}

// NCHW fp32 -> NHWC bf16 hi/lo (optional ReLU)
__global__ __launch_bounds__(256) void cvt_nhwc(const float* __restrict__ src,
                                                __nv_bfloat16* __restrict__ hi,
                                                __nv_bfloat16* __restrict__ lo,
                                                int relu) {
    __shared__ __nv_bfloat16 sh[32][66], sl[32][66];
    const int p0 = blockIdx.x * 64, c0 = blockIdx.y * 32, b = blockIdx.z;
    const int t = threadIdx.x;
    #pragma unroll
    for (int it = 0; it < 8; it++) {
        int idx = t + it * 256;
        int c = idx >> 6, p = idx & 63;
        float v = src[((b * 128 + c0 + c) * 4096) + p0 + p];
        if (relu) v = fmaxf(v, 0.f);
        __nv_bfloat16 h = __float2bfloat16(v);
        sh[c][p] = h;
        sl[c][p] = __float2bfloat16(v - __bfloat162float(h));
    }
    __syncthreads();
    #pragma unroll
    for (int it = 0; it < 8; it++) {
        int idx = t + it * 256;
        int c = idx & 31, p = idx >> 5;
        size_t d = ((size_t)(b * 4096 + p0 + p) * 128) + c0 + c;
        hi[d] = sh[c][p];
        lo[d] = sl[c][p];
    }
}

// ---------------------------------------------------------------------------
// conv3x3 via mma.sync bf16 (decoder)
// ---------------------------------------------------------------------------
__global__ __launch_bounds__(256) void conv3x3_mma(
        const __nv_bfloat16* __restrict__ hi,
        const __nv_bfloat16* __restrict__ lo,
        const uint4* __restrict__ wt,
        const float* __restrict__ bias,
        float* __restrict__ out) {
    extern __shared__ char smem[];
    const uint32_t sbase = smem_u32(smem);
    const int tid = threadIdx.x;
    const int lane = tid & 31, warp = tid >> 5;
    const int b = blockIdx.x >> 5;
    const int y0 = (blockIdx.x & 31) * 2;
    const int mtile = (warp & 3) * 32;
    const int ntile = (warp >> 2) * 64;
    float* sb = (float*)(smem + 131072);
    if (tid < 128) sb[tid] = bias[tid];

    float acc[2][8][4];
    #pragma unroll
    for (int mi = 0; mi < 2; mi++)
        #pragma unroll
        for (int j = 0; j < 8; j++)
            #pragma unroll
            for (int q = 0; q < 4; q++) acc[mi][j][q] = 0.f;

    const int px = tid >> 1, half = tid & 1;
    const uint32_t rA = (uint32_t)(mtile + (lane & 15));
    const uint32_t cl = (uint32_t)(lane >> 4);
    const uint32_t swz = (uint32_t)(lane & 7);
    const uint32_t wrow = (uint32_t)((lane & 7) + ((lane >> 4) << 3));
    const uint32_t wq   = (uint32_t)((ntile >> 3) + ((lane >> 3) & 1));

    #pragma unroll 1
    for (int tap = 0; tap < 9; tap++) {
        const int dy = tap / 3 - 1, dx = tap % 3 - 1;
        __syncthreads();
        {
            const int yy = y0 + (px >> 6) + dy;
            const int xx = (px & 63) + dx;
            const bool valid = ((unsigned)yy < 64u) && ((unsigned)xx < 64u);
            const size_t rowoff = valid ? ((size_t)((b << 12) + yy * 64 + xx) * 128) : 0;
            const uint4* qh = (const uint4*)(hi + rowoff);
            const uint4* ql = (const uint4*)(lo + rowoff);
            uint4* AH = (uint4*)smem;
            uint4* AL = (uint4*)(smem + 32768);
            const uint4 z = make_uint4(0, 0, 0, 0);
            #pragma unroll
            for (int j = 0; j < 8; j++) {
                int cidx = half * 8 + j;
                int si = px * 16 + (cidx ^ (px & 7));
                AH[si] = valid ? qh[cidx] : z;
                AL[si] = valid ? ql[cidx] : z;
            }
        }
        {
            const uint4* wsrc = wt + (size_t)tap * 4096;
            uint4* WD = (uint4*)(smem + 65536);
            #pragma unroll
            for (int i = 0; i < 16; i++) WD[tid + i * 256] = wsrc[tid + i * 256];
        }
        __syncthreads();
        #pragma unroll 1
        for (int pass = 0; pass < 3; pass++) {
            const uint32_t Ab = sbase + (pass < 2 ? 0u : 32768u) + rA * 256u;
            const uint32_t Wb = sbase + 65536u + (pass == 1 ? 32768u : 0u);
            #pragma unroll
            for (int ks = 0; ks < 8; ks++) {
                const uint32_t ch = (((uint32_t)(2 * ks) + cl) ^ swz) * 16u;
                uint32_t a0[4], a1[4];
                ldsm_x4(a0, Ab + ch);
                ldsm_x4(a1, Ab + 4096u + ch);
                const uint32_t WbRow = Wb + ((uint32_t)ks * 16u + wrow) * 256u;
                uint32_t bf0[4], bf1[4], bf2[4], bf3[4];
                ldsm_x4t(bf0, WbRow + (((wq + 0u) ^ swz) * 16u));
                ldsm_x4t(bf1, WbRow + (((wq + 2u) ^ swz) * 16u));
                ldsm_x4t(bf2, WbRow + (((wq + 4u) ^ swz) * 16u));
                ldsm_x4t(bf3, WbRow + (((wq + 6u) ^ swz) * 16u));
                #pragma unroll
                for (int j = 0; j < 8; j++) {
                    const uint32_t* f = (j >> 1) == 0 ? bf0 : ((j >> 1) == 1 ? bf1 : ((j >> 1) == 2 ? bf2 : bf3));
                    uint32_t b0 = (j & 1) ? f[1] : f[0];
                    uint32_t b1 = (j & 1) ? f[3] : f[2];
                    mma16816(acc[0][j], a0, b0, b1);
                    mma16816(acc[1][j], a1, b0, b1);
                }
            }
        }
    }

    const int m_r = lane >> 2, n_c = (lane & 3) * 2;
    const int sp0 = y0 * 64;
    #pragma unroll
    for (int mi = 0; mi < 2; mi++) {
        #pragma unroll
        for (int j = 0; j < 8; j++) {
            int m = mtile + mi * 16 + m_r;
            int n = ntile + j * 8 + n_c;
            float* o0 = out + ((size_t)(b * 128 + n) << 12) + sp0 + m;
            float* o1 = o0 + 4096;
            o0[0] = acc[mi][j][0] + sb[n];
            o1[0] = acc[mi][j][1] + sb[n + 1];
            o0[8] = acc[mi][j][2] + sb[n];
            o1[8] = acc[mi][j][3] + sb[n + 1];
        }
    }
}

// ---------------------------------------------------------------------------
// dt1 via mma.sync bf16: ConvTranspose 4x4 s2 p1 as 4 parity classes
// (oy%2, ox%2), each 4 taps over the 64x64 input. blockIdx.y = parity.
// Output 128x128 NCHW fp32 with bias+ReLU.
// ---------------------------------------------------------------------------
__global__ __launch_bounds__(256) void dt1_mma(
        const __nv_bfloat16* __restrict__ hi,
        const __nv_bfloat16* __restrict__ lo,
        const uint4* __restrict__ wtb,    // base of 16 parity-tap tiles
        const float* __restrict__ bias,
        float* __restrict__ out) {
    extern __shared__ char smem[];
    const uint32_t sbase = smem_u32(smem);
    const int tid = threadIdx.x;
    const int lane = tid & 31, warp = tid >> 5;
    const int b = blockIdx.x >> 5;
    const int y0 = (blockIdx.x & 31) * 2;
    const int p = blockIdx.y;
    const int sy = p >> 1, sx = p & 1;
    const uint4* wt = wtb + (size_t)p * 4 * 4096;
    const int mtile = (warp & 3) * 32;
    const int ntile = (warp >> 2) * 64;
    float* sb = (float*)(smem + 131072);
    if (tid < 128) sb[tid] = bias[tid];

    float acc[2][8][4];
    #pragma unroll
    for (int mi = 0; mi < 2; mi++)
        #pragma unroll
        for (int j = 0; j < 8; j++)
            #pragma unroll
            for (int q = 0; q < 4; q++) acc[mi][j][q] = 0.f;

    const int px = tid >> 1, half = tid & 1;
    const uint32_t rA = (uint32_t)(mtile + (lane & 15));
    const uint32_t cl = (uint32_t)(lane >> 4);
    const uint32_t swz = (uint32_t)(lane & 7);
    const uint32_t wrow = (uint32_t)((lane & 7) + ((lane >> 4) << 3));
    const uint32_t wq   = (uint32_t)((ntile >> 3) + ((lane >> 3) & 1));

    #pragma unroll 1
    for (int t = 0; t < 4; t++) {
        const int ty = t >> 1, tx = t & 1;
        const int dy = ty == 0 ? 0 : (sy ? 1 : -1);
        const int dx = tx == 0 ? 0 : (sx ? 1 : -1);
        __syncthreads();
        {
            const int yy = y0 + (px >> 6) + dy;
            const int xx = (px & 63) + dx;
            const bool valid = ((unsigned)yy < 64u) && ((unsigned)xx < 64u);
            const size_t rowoff = valid ? ((size_t)((b << 12) + yy * 64 + xx) * 128) : 0;
            const uint4* qh = (const uint4*)(hi + rowoff);
            const uint4* ql = (const uint4*)(lo + rowoff);
            uint4* AH = (uint4*)smem;
            uint4* AL = (uint4*)(smem + 32768);
            const uint4 z = make_uint4(0, 0, 0, 0);
            #pragma unroll
            for (int j = 0; j < 8; j++) {
                int cidx = half * 8 + j;
                int si = px * 16 + (cidx ^ (px & 7));
                AH[si] = valid ? qh[cidx] : z;
                AL[si] = valid ? ql[cidx] : z;
            }
        }
        {
            const uint4* wsrc = wt + (size_t)t * 4096;
            uint4* WD = (uint4*)(smem + 65536);
            #pragma unroll
            for (int i = 0; i < 16; i++) WD[tid + i * 256] = wsrc[tid + i * 256];
        }
        __syncthreads();
        #pragma unroll 1
        for (int pass = 0; pass < 3; pass++) {
            const uint32_t Ab = sbase + (pass < 2 ? 0u : 32768u) + rA * 256u;
            const uint32_t Wb = sbase + 65536u + (pass == 1 ? 32768u : 0u);
            #pragma unroll
            for (int ks = 0; ks < 8; ks++) {
                const uint32_t ch = (((uint32_t)(2 * ks) + cl) ^ swz) * 16u;
                uint32_t a0[4], a1[4];
                ldsm_x4(a0, Ab + ch);
                ldsm_x4(a1, Ab + 4096u + ch);
                const uint32_t WbRow = Wb + ((uint32_t)ks * 16u + wrow) * 256u;
                uint32_t bf0[4], bf1[4], bf2[4], bf3[4];
                ldsm_x4t(bf0, WbRow + (((wq + 0u) ^ swz) * 16u));
                ldsm_x4t(bf1, WbRow + (((wq + 2u) ^ swz) * 16u));
                ldsm_x4t(bf2, WbRow + (((wq + 4u) ^ swz) * 16u));
                ldsm_x4t(bf3, WbRow + (((wq + 6u) ^ swz) * 16u));
                #pragma unroll
                for (int j = 0; j < 8; j++) {
                    const uint32_t* f = (j >> 1) == 0 ? bf0 : ((j >> 1) == 1 ? bf1 : ((j >> 1) == 2 ? bf2 : bf3));
                    uint32_t b0 = (j & 1) ? f[1] : f[0];
                    uint32_t b1 = (j & 1) ? f[3] : f[2];
                    mma16816(acc[0][j], a0, b0, b1);
                    mma16816(acc[1][j], a1, b0, b1);
                }
            }
        }
    }

    // epilogue: pixel m -> (qy = y0 + m/64, qx = m%64); oy = 2qy+sy, ox = 2qx+sx
    const int m_r = lane >> 2, n_c = (lane & 3) * 2;
    #pragma unroll
    for (int mi = 0; mi < 2; mi++) {
        #pragma unroll
        for (int j = 0; j < 8; j++) {
            int m = mtile + mi * 16 + m_r;
            int n = ntile + j * 8 + n_c;
            int qy = y0 + (m >> 6), qx = m & 63;
            size_t rowbase = ((size_t)(b * 128 + n) << 14) + (size_t)(2 * qy + sy) * 128 + sx;
            float* o0 = out + rowbase;
            float* o1 = o0 + 16384;        // co n+1
            float bn0 = sb[n], bn1 = sb[n + 1];
            o0[2*qx]        = fmaxf(acc[mi][j][0] + bn0, 0.f);
            o1[2*qx]        = fmaxf(acc[mi][j][1] + bn1, 0.f);
            o0[2*(qx + 8)]  = fmaxf(acc[mi][j][2] + bn0, 0.f);
            o1[2*(qx + 8)]  = fmaxf(acc[mi][j][3] + bn1, 0.f);
        }
    }
}

// ---------------------------------------------------------------------------
// e1: conv 3->128, k4 s2 p1, 256x256 -> 128x128, ReLU
// ---------------------------------------------------------------------------
__global__ __launch_bounds__(256) void e1_k(const float* __restrict__ x,
                                            const float* __restrict__ w,
                                            const float* __restrict__ bias,
                                            float* __restrict__ out) {
    __shared__ float ws[128*3*16];
    for (int i = threadIdx.x; i < 128*3*16; i += 256) ws[i] = w[i];
    __syncthreads();
    int g = blockIdx.x * 256 + threadIdx.x;
    int ox = g & 127, oy = (g >> 7) & 127, co = (g >> 14) & 127, b = g >> 21;
    float acc = bias[co];
    int iy0 = 2*oy - 1, ix0 = 2*ox - 1;
    #pragma unroll
    for (int ci = 0; ci < 3; ci++) {
        const float* xp = x + (b*3 + ci) * 65536;
        const float* wp = ws + (co*3 + ci) * 16;
        #pragma unroll
        for (int ky = 0; ky < 4; ky++) {
            int iy = iy0 + ky;
            if ((unsigned)iy < 256u) {
                #pragma unroll
                for (int kx = 0; kx < 4; kx++) {
                    int ix = ix0 + kx;
                    if ((unsigned)ix < 256u)
                        acc = fmaf(xp[iy*256 + ix], wp[ky*4 + kx], acc);
                }
            }
        }
    }
    out[g] = fmaxf(acc, 0.f);
}

// ---------------------------------------------------------------------------
// e2: conv 128->128, k4 s2 p1 (scalar, encoder — bit-stable)
// ---------------------------------------------------------------------------
__global__ __launch_bounds__(128) void conv4s2_k(const float* __restrict__ in,
                                                 const float* __restrict__ wT,
                                                 const float* __restrict__ bias,
                                                 float* __restrict__ out) {
    const int co = threadIdx.x;
    const int ox0 = blockIdx.x * 8, oy0 = blockIdx.y * 8, b = blockIdx.z;
    __shared__ float s[8][18][20];
    float acc[64];
    {
        float bv = bias[co];
        #pragma unroll
        for (int i = 0; i < 64; i++) acc[i] = bv;
    }
    const int iy0 = oy0*2 - 1, ix0 = ox0*2 - 1;
    for (int cc = 0; cc < 128; cc += 8) {
        __syncthreads();
        for (int idx = co; idx < 8*324; idx += 128) {
            int ci = idx / 324, rr = idx % 324, r = rr / 18, cl = rr % 18;
            int iy = iy0 + r, ix = ix0 + cl;
            float v = 0.f;
            if ((unsigned)iy < 128u && (unsigned)ix < 128u)
                v = in[((b*128 + cc + ci) * 128 + iy) * 128 + ix];
            s[ci][r][cl] = v;
        }
        __syncthreads();
        #pragma unroll 1
        for (int ci = 0; ci < 8; ci++) {
            float wt[16];
            const float* wp = wT + (cc + ci) * 16 * 128 + co;
            #pragma unroll
            for (int k = 0; k < 16; k++) wt[k] = wp[k*128];
            #pragma unroll
            for (int r = 0; r < 18; r++) {
                float4 f0 = *(const float4*)&s[ci][r][0];
                float4 f1 = *(const float4*)&s[ci][r][4];
                float4 f2 = *(const float4*)&s[ci][r][8];
                float4 f3 = *(const float4*)&s[ci][r][12];
                float4 f4 = *(const float4*)&s[ci][r][16];
                float row[18] = {f0.x,f0.y,f0.z,f0.w, f1.x,f1.y,f1.z,f1.w,
                                 f2.x,f2.y,f2.z,f2.w, f3.x,f3.y,f3.z,f3.w,
                                 f4.x,f4.y};
                #pragma unroll
                for (int ky = 0; ky < 4; ky++) {
                    if (((r - ky) & 1) == 0) {
                        int py = (r - ky) >> 1;
                        if (py >= 0 && py < 8) {
                            #pragma unroll
                            for (int px = 0; px < 8; px++) {
                                float a = acc[py*8 + px];
                                a = fmaf(row[2*px + 0], wt[ky*4 + 0], a);
                                a = fmaf(row[2*px + 1], wt[ky*4 + 1], a);
                                a = fmaf(row[2*px + 2], wt[ky*4 + 2], a);
                                a = fmaf(row[2*px + 3], wt[ky*4 + 3], a);
                                acc[py*8 + px] = a;
                            }
                        }
                    }
                }
            }
        }
    }
    float* op = out + ((b*128 + co) * 64 + oy0) * 64 + ox0;
    #pragma unroll
    for (int py = 0; py < 8; py++)
        #pragma unroll
        for (int px = 0; px < 8; px++)
            op[py*64 + px] = fmaxf(acc[py*8 + px], 0.f);
}

// ---------------------------------------------------------------------------
// conv3x3 scalar (encoder), bit-identical
// ---------------------------------------------------------------------------
template<bool RELU_IN>
__global__ __launch_bounds__(128) void conv3x3_k(const float* __restrict__ in,
                                                 const float* __restrict__ wT,
                                                 const float* __restrict__ bias,
                                                 float* __restrict__ out) {
    const int co = threadIdx.x;
    const int ox0 = blockIdx.x * 8, oy0 = blockIdx.y * 8, b = blockIdx.z;
    __shared__ float s[16][10][12];
    float acc[64];
    {
        float bv = bias[co];
        #pragma unroll
        for (int i = 0; i < 64; i++) acc[i] = bv;
    }
    for (int cc = 0; cc < 128; cc += 16) {
        __syncthreads();
        for (int idx = co; idx < 16*100; idx += 128) {
            int ci = idx / 100, rr = idx % 100, r = rr / 10, cl = rr % 10;
            int iy = oy0 - 1 + r, ix = ox0 - 1 + cl;
            float v = 0.f;
            if ((unsigned)iy < 64u && (unsigned)ix < 64u) {
                v = in[((b*128 + cc + ci) * 64 + iy) * 64 + ix];
                if (RELU_IN) v = fmaxf(v, 0.f);
            }
            s[ci][r][cl] = v;
        }
        __syncthreads();
        #pragma unroll 1
        for (int ci = 0; ci < 16; ci++) {
            float wt[9];
            const float* wp = wT + (cc + ci) * 9 * 128 + co;
            #pragma unroll
            for (int k = 0; k < 9; k++) wt[k] = wp[k*128];
            #pragma unroll
            for (int r = 0; r < 10; r++) {
                float4 f0 = *(const float4*)&s[ci][r][0];
                float4 f1 = *(const float4*)&s[ci][r][4];
                float4 f2 = *(const float4*)&s[ci][r][8];
                float row[10] = {f0.x,f0.y,f0.z,f0.w, f1.x,f1.y,f1.z,f1.w,
                                 f2.x,f2.y};
                #pragma unroll
                for (int ky = 0; ky < 3; ky++) {
                    int py = r - ky;
                    if (py >= 0 && py < 8) {
                        #pragma unroll
                        for (int px = 0; px < 8; px++) {
                            float a = acc[py*8 + px];
                            a = fmaf(row[px + 0], wt[ky*3 + 0], a);
                            a = fmaf(row[px + 1], wt[ky*3 + 1], a);
                            a = fmaf(row[px + 2], wt[ky*3 + 2], a);
                            acc[py*8 + px] = a;
                        }
                    }
                }
            }
        }
    }
    float* op = out + ((b*128 + co) * 64 + oy0) * 64 + ox0;
    #pragma unroll
    for (int py = 0; py < 8; py++)
        #pragma unroll
        for (int px = 0; px < 8; px++)
            op[py*64 + px] = acc[py*8 + px];
}

// ---------------------------------------------------------------------------
// conv1x1 + input ReLU + residual
// ---------------------------------------------------------------------------
__global__ __launch_bounds__(128) void conv1x1_res_k(const float* __restrict__ in,
                                                     const float* __restrict__ wT,
                                                     const float* __restrict__ bias,
                                                     const float* __restrict__ res,
                                                     float* __restrict__ out) {
    const int co = threadIdx.x;
    const int b = blockIdx.x >> 6;
    const int p0 = (blockIdx.x & 63) * 64;
    __shared__ float s[32][64];
    float acc[64];
    {
        float bv = bias[co];
        #pragma unroll
        for (int i = 0; i < 64; i++) acc[i] = bv;
    }
    for (int cc = 0; cc < 128; cc += 32) {
        __syncthreads();
        for (int idx = co; idx < 32*64; idx += 128) {
            int ci = idx >> 6, p = idx & 63;
            float v = in[(b*128 + cc + ci) * 4096 + p0 + p];
            s[ci][p] = fmaxf(v, 0.f);
        }
        __syncthreads();
        #pragma unroll 1
        for (int ci = 0; ci < 32; ci++) {
            float wv = wT[(cc + ci) * 128 + co];
            const float4* sp = (const float4*)s[ci];
            #pragma unroll
            for (int p4 = 0; p4 < 16; p4++) {
                float4 v = sp[p4];
                acc[4*p4 + 0] = fmaf(v.x, wv, acc[4*p4 + 0]);
                acc[4*p4 + 1] = fmaf(v.y, wv, acc[4*p4 + 1]);
                acc[4*p4 + 2] = fmaf(v.z, wv, acc[4*p4 + 2]);
                acc[4*p4 + 3] = fmaf(v.w, wv, acc[4*p4 + 3]);
            }
        }
    }
    const float* rp = res + (b*128 + co) * 4096 + p0;
    float* op = out + (b*128 + co) * 4096 + p0;
    #pragma unroll
    for (int p = 0; p < 64; p++) op[p] = rp[p] + acc[p];
}

// ---------------------------------------------------------------------------
// VQ (reference-numerics replica) — unchanged
// ---------------------------------------------------------------------------
__global__ __launch_bounds__(256) void vq_k(const float* __restrict__ ze,
                                            const float* __restrict__ cb,
                                            float* __restrict__ zq) {
    const int b = blockIdx.x >> 6;
    const int p0 = (blockIdx.x & 63) * 64;
    __shared__ float zs[128][64];
    __shared__ float cs[16][128];
    __shared__ float zzs[64];
    __shared__ float ees[512];
    __shared__ float rb1[256]; __shared__ int ri1[256];
    __shared__ int   finalidx[64];
    const int t = threadIdx.x;
    const float* zb = ze + b * 128 * 4096 + p0;
    for (int idx = t; idx < 128*64; idx += 256) {
        int c = idx >> 6, p = idx & 63;
        zs[c][p] = zb[c*4096 + p];
    }
    for (int k = t; k < 512; k += 256) {
        const float* cp = cb + k * 128;
        double acc = 0.0;
        for (int c = 0; c < 128; c++) { double e = (double)cp[c]; acc += e * e; }
        ees[k] = (float)acc;
    }
    __syncthreads();
    if (t < 64) {
        double acc = 0.0;
        for (int c = 0; c < 128; c++) { double z = (double)zs[c][t]; acc += z * z; }
        zzs[t] = (float)acc;
    }
    __syncthreads();

    float b1 = 3.4e38f; int i1 = 0x7fffffff;
    const int pos = t & 63, cg = t >> 6;
    const float zz = zzs[pos];
    for (int k0 = 0; k0 < 512; k0 += 16) {
        __syncthreads();
        for (int idx = t; idx < 16*128; idx += 256)
            cs[idx >> 7][idx & 127] = cb[k0*128 + idx];
        __syncthreads();
        float dot0 = 0.f, dot1 = 0.f, dot2 = 0.f, dot3 = 0.f;
        const float4* e0 = (const float4*)cs[cg + 0];
        const float4* e1 = (const float4*)cs[cg + 4];
        const float4* e2 = (const float4*)cs[cg + 8];
        const float4* e3 = (const float4*)cs[cg + 12];
        #pragma unroll 4
        for (int c4 = 0; c4 < 32; c4++) {
            float z0 = zs[4*c4 + 0][pos];
            float z1 = zs[4*c4 + 1][pos];
            float z2 = zs[4*c4 + 2][pos];
            float z3 = zs[4*c4 + 3][pos];
            float4 a = e0[c4], bb = e1[c4], cA = e2[c4], dd = e3[c4];
            dot0 = __fmaf_rn(z0, a.x, dot0);  dot0 = __fmaf_rn(z1, a.y, dot0);
            dot0 = __fmaf_rn(z2, a.z, dot0);  dot0 = __fmaf_rn(z3, a.w, dot0);
            dot1 = __fmaf_rn(z0, bb.x, dot1); dot1 = __fmaf_rn(z1, bb.y, dot1);
            dot1 = __fmaf_rn(z2, bb.z, dot1); dot1 = __fmaf_rn(z3, bb.w, dot1);
            dot2 = __fmaf_rn(z0, cA.x, dot2); dot2 = __fmaf_rn(z1, cA.y, dot2);
            dot2 = __fmaf_rn(z2, cA.z, dot2); dot2 = __fmaf_rn(z3, cA.w, dot2);
            dot3 = __fmaf_rn(z0, dd.x, dot3); dot3 = __fmaf_rn(z1, dd.y, dot3);
            dot3 = __fmaf_rn(z2, dd.z, dot3); dot3 = __fmaf_rn(z3, dd.w, dot3);
        }
        float dts[4] = {dot0, dot1, dot2, dot3};
        #pragma unroll
        for (int m = 0; m < 4; m++) {
            int gidx = k0 + cg + 4*m;
            float d = __fadd_rn(__fsub_rn(zz, __fmul_rn(2.f, dts[m])), ees[gidx]);
            if (d < b1) { b1 = d; i1 = gidx; }
        }
    }
    rb1[t] = b1; ri1[t] = i1;
    __syncthreads();
    if (t < 64) {
        float B1 = rb1[t]; int I1 = ri1[t];
        #pragma unroll
        for (int g = 1; g < 4; g++) {
            float v = rb1[t + 64*g]; int vi = ri1[t + 64*g];
            if (v < B1 || (v == B1 && vi < I1)) { B1 = v; I1 = vi; }
        }
        finalidx[t] = I1;
    }
    __syncthreads();
    float* zqb = zq + b * 128 * 4096 + p0;
    for (int idx = t; idx < 128*64; idx += 256) {
        int c = idx >> 6, p = idx & 63;
        zqb[c*4096 + p] = cb[finalidx[p]*128 + c];
    }
}

// ---------------------------------------------------------------------------
// dt2: ConvTranspose2d 128->3, k4 s2 p1, 128x128 -> 256x256
// ---------------------------------------------------------------------------
__global__ __launch_bounds__(256) void dt2_k(const float* __restrict__ in,
                                             const float* __restrict__ w,
                                             const float* __restrict__ bias,
                                             float* __restrict__ out) {
    __shared__ float ws[128*3*16];
    for (int i = threadIdx.x; i < 128*3*16; i += 256) ws[i] = w[i];
    __syncthreads();
    int g = blockIdx.x * 256 + threadIdx.x;
    int ox = g & 255, oy = (g >> 8) & 255, b = g >> 16;
    float a0 = bias[0], a1 = bias[1], a2 = bias[2];
    const int ky0 = (oy + 1) & 1, kx0 = (ox + 1) & 1;
    const int iyh = (oy + 1 - ky0) >> 1, ixh = (ox + 1 - kx0) >> 1;
    #pragma unroll 4
    for (int ci = 0; ci < 128; ci++) {
        const float* ip = in + ((b*128 + ci) << 14);
        const float* wp = ws + ci * 48;
        #pragma unroll
        for (int dy = 0; dy < 2; dy++) {
            int iy = iyh - dy, ky = ky0 + 2*dy;
            if ((unsigned)iy < 128u) {
                #pragma unroll
                for (int dx = 0; dx < 2; dx++) {
                    int ix = ixh - dx, kx = kx0 + 2*dx;
                    if ((unsigned)ix < 128u) {
                        float v = ip[iy*128 + ix];
                        int wk = ky*4 + kx;
                        a0 = fmaf(v, wp[wk],      a0);
                        a1 = fmaf(v, wp[16 + wk], a1);
                        a2 = fmaf(v, wp[32 + wk], a2);
                    }
                }
            }
        }
    }
    int sp = oy*256 + ox;
    out[(b*3 + 0) * 65536 + sp] = a0;
    out[(b*3 + 1) * 65536 + sp] = a1;
    out[(b*3 + 2) * 65536 + sp] = a2;
}

// ---------------------------------------------------------------------------

extern "C" void kernel_launch(void* const* d_in, const int* in_sizes, int n_in,
                              void* d_out, int out_size) {
    const float* x      = (const float*)d_in[0];
    const float* e1_w   = (const float*)d_in[1];  const float* e1_b = (const float*)d_in[2];
    const float* e2_w   = (const float*)d_in[3];  const float* e2_b = (const float*)d_in[4];
    const float* e3_w   = (const float*)d_in[5];  const float* e3_b = (const float*)d_in[6];
    const float* er1a_w = (const float*)d_in[7];  const float* er1a_b = (const float*)d_in[8];
    const float* er1b_w = (const float*)d_in[9];  const float* er1b_b = (const float*)d_in[10];
    const float* er2a_w = (const float*)d_in[11]; const float* er2a_b = (const float*)d_in[12];
    const float* er2b_w = (const float*)d_in[13]; const float* er2b_b = (const float*)d_in[14];
    const float* codebook = (const float*)d_in[15];
    const float* d1_w   = (const float*)d_in[16]; const float* d1_b = (const float*)d_in[17];
    const float* dr1a_w = (const float*)d_in[18]; const float* dr1a_b = (const float*)d_in[19];
    const float* dr1b_w = (const float*)d_in[20]; const float* dr1b_b = (const float*)d_in[21];
    const float* dr2a_w = (const float*)d_in[22]; const float* dr2a_b = (const float*)d_in[23];
    const float* dr2b_w = (const float*)d_in[24]; const float* dr2b_b = (const float*)d_in[25];
    const float* dt1_w  = (const float*)d_in[26]; const float* dt1_b = (const float*)d_in[27];
    const float* dt2_w  = (const float*)d_in[28]; const float* dt2_b = (const float*)d_in[29];

    float* out   = (float*)d_out;
    float* xhat  = out;
    float* ze    = out + XHAT_ELEMS;
    float* zq    = out + XHAT_ELEMS + ZE_ELEMS;

    float* A;  cudaGetSymbolAddress((void**)&A,  g_A);
    float* Bf; cudaGetSymbolAddress((void**)&Bf, g_B);
    float* Cf; cudaGetSymbolAddress((void**)&Cf, g_C);
    float* Df; cudaGetSymbolAddress((void**)&Df, g_D);
    float* Tf; cudaGetSymbolAddress((void**)&Tf, g_T);
    float* W;  cudaGetSymbolAddress((void**)&W,  g_W);
    __nv_bfloat16* Hi; cudaGetSymbolAddress((void**)&Hi, g_Hi);
    __nv_bfloat16* Lo; cudaGetSymbolAddress((void**)&Lo, g_Lo);
    uint4* WT; cudaGetSymbolAddress((void**)&WT, g_WT);

    cudaFuncSetAttribute(conv3x3_mma, cudaFuncAttributeMaxDynamicSharedMemorySize, 131584);
    cudaFuncSetAttribute(dt1_mma, cudaFuncAttributeMaxDynamicSharedMemorySize, 131584);

    // weight prep
    tpose_all<<<4032, 256>>>(e3_w, er1a_w, er2a_w, e2_w, dt1_w,
                             er1b_w, er2b_w, dr1b_w, dr2b_w, W);
    wprep3<<<1728, 256>>>(d1_w, dr1a_w, dr2a_w);
    wprep_dt1<<<1024, 256>>>(dt1_w);

    dim3 tile64(8, 8, BATCH);
    dim3 cvtg(64, 4, 16);
    dim3 dt1g(16*32, 4);

    // encoder (scalar, bit-identical)
    e1_k<<<(16*128*128*128)/256, 256>>>(x, e1_w, e1_b, A);
    conv4s2_k<<<tile64, 128>>>(A, W + WE2_OFF, e2_b, Bf);
    conv3x3_k<false><<<tile64, 128>>>(Bf, W + W3_OFF(0), e3_b, Cf);
    conv3x3_k<true><<<tile64, 128>>>(Cf, W + W3_OFF(1), er1a_b, Tf);
    conv1x1_res_k<<<16*64, 128>>>(Tf, W + W1_OFF(0), er1b_b, Cf, Df);
    conv3x3_k<true><<<tile64, 128>>>(Df, W + W3_OFF(2), er2a_b, Tf);
    conv1x1_res_k<<<16*64, 128>>>(Tf, W + W1_OFF(1), er2b_b, Df, ze);
    // VQ
    vq_k<<<16*64, 256>>>(ze, codebook, zq);
    // decoder: mma tensor cores
    cvt_nhwc<<<cvtg, 256>>>(zq, Hi, Lo, 0);
    conv3x3_mma<<<512, 256, 131584>>>(Hi, Lo, WT + (size_t)0*9*4096, d1_b, Cf);
    cvt_nhwc<<<cvtg, 256>>>(Cf, Hi, Lo, 1);
    conv3x3_mma<<<512, 256, 131584>>>(Hi, Lo, WT + (size_t)1*9*4096, dr1a_b, Tf);
    conv1x1_res_k<<<16*64, 128>>>(Tf, W + W1_OFF(2), dr1b_b, Cf, Df);
    cvt_nhwc<<<cvtg, 256>>>(Df, Hi, Lo, 1);
    conv3x3_mma<<<512, 256, 131584>>>(Hi, Lo, WT + (size_t)2*9*4096, dr2a_b, Tf);
    conv1x1_res_k<<<16*64, 128>>>(Tf, W + W1_OFF(3), dr2b_b, Df, Bf);
    cvt_nhwc<<<cvtg, 256>>>(Bf, Hi, Lo, 0);
    dt1_mma<<<dt1g, 256, 131584>>>(Hi, Lo, WT + WT_DT1_BASE, dt1_b, A);
    dt2_k<<<(16*256*256)/256, 256>>>(A, dt2_w, dt2_b, xhat);
}

// round 17
// speedup vs baseline: 2.0946x; 1.0882x over previous
#include <cuda_runtime.h>
#include <cuda_bf16.h>
#include <cstdint>

// ---------------------------------------------------------------------------
// VQ-VAE forward. Encoder: fp32 scalar (bit-stable for VQ). Decoder 3x3 convs
// AND dt1: warp mma.sync bf16 hi/lo split (3-pass).
// R15: e1 retiled (co-parallel, smem x-tile) — bit-identical accumulation.
// d_out: x_hat | ze | zq
// ---------------------------------------------------------------------------

#define BATCH 16
#define XHAT_ELEMS (16*3*256*256)
#define ZE_ELEMS   (16*128*64*64)

__device__ float g_A[16*128*128*128];
__device__ float g_B[ZE_ELEMS];
__device__ float g_C[ZE_ELEMS];
__device__ float g_D[ZE_ELEMS];
__device__ float g_T[ZE_ELEMS];
__device__ float g_W[1474560];             // scalar transposed weights
__device__ __nv_bfloat16 g_Hi[ZE_ELEMS];   // NHWC hi plane
__device__ __nv_bfloat16 g_Lo[ZE_ELEMS];   // NHWC lo plane
__device__ uint4 g_WT[(3*9 + 16) * 4096];  // mma weights
#define WT_DT1_BASE (27 * 4096)

#define W3_OFF(i)  ((i) * 147456)
#define WE2_OFF    884736
#define WDT1_OFF   1146880
#define W1_OFF(i)  (1409024 + (i) * 16384)

// ============================ mma helpers ==================================
__device__ __forceinline__ uint32_t smem_u32(const void* p) {
    uint32_t a;
    asm("{ .reg .u64 t; cvta.to.shared.u64 t, %1; cvt.u32.u64 %0, t; }" : "=r"(a) : "l"(p));
    return a;
}
__device__ __forceinline__ void ldsm_x4(uint32_t* r, uint32_t addr) {
    asm volatile("ldmatrix.sync.aligned.m8n8.x4.shared.b16 {%0,%1,%2,%3}, [%4];"
        : "=r"(r[0]), "=r"(r[1]), "=r"(r[2]), "=r"(r[3]) : "r"(addr));
}
__device__ __forceinline__ void ldsm_x4t(uint32_t* r, uint32_t addr) {
    asm volatile("ldmatrix.sync.aligned.m8n8.x4.trans.shared.b16 {%0,%1,%2,%3}, [%4];"
        : "=r"(r[0]), "=r"(r[1]), "=r"(r[2]), "=r"(r[3]) : "r"(addr));
}
__device__ __forceinline__ void mma16816(float* c, const uint32_t* a,
                                         uint32_t b0, uint32_t b1) {
    asm volatile(
        "mma.sync.aligned.m16n8k16.row.col.f32.bf16.bf16.f32 "
        "{%0,%1,%2,%3}, {%4,%5,%6,%7}, {%8,%9}, {%0,%1,%2,%3};"
        : "+f"(c[0]), "+f"(c[1]), "+f"(c[2]), "+f"(c[3])
        : "r"(a[0]), "r"(a[1]), "r"(a[2]), "r"(a[3]), "r"(b0), "r"(b1));
}

// ============================ prep kernels =================================
__global__ __launch_bounds__(256) void tpose_all(
        const float* __restrict__ e3, const float* __restrict__ er1a,
        const float* __restrict__ er2a, const float* __restrict__ e2,
        const float* __restrict__ dt1, const float* __restrict__ b1,
        const float* __restrict__ b2, const float* __restrict__ b3,
        const float* __restrict__ b4, float* __restrict__ dst) {
    int i = blockIdx.x * 256 + threadIdx.x;
    if (i < 442368) {
        int layer = i / 147456, rem = i - layer * 147456;
        const float* s = layer == 0 ? e3 : (layer == 1 ? er1a : er2a);
        int co = rem / 1152, r = rem - co * 1152;
        dst[W3_OFF(layer) + r * 128 + co] = s[rem];
    } else if (i < 704512) {
        int j = i - 442368;
        int co = j / 2048, r = j - co * 2048;
        dst[WE2_OFF + r * 128 + co] = e2[j];
    } else if (i < 966656) {
        int j = i - 704512;
        int ci = j / 2048, r = j - ci * 2048;
        int co = r / 16, k = r - co * 16;
        dst[WDT1_OFF + (ci * 16 + k) * 128 + co] = dt1[j];
    } else {
        int j = i - 966656;
        int layer = j >> 14, rem = j & 16383;
        const float* s = layer == 0 ? b1 : (layer == 1 ? b2 : (layer == 2 ? b3 : b4));
        int co = rem >> 7, ci = rem & 127;
        dst[W1_OFF(layer) + ci * 128 + co] = s[rem];
    }
}

__global__ __launch_bounds__(256) void wprep3(const float* __restrict__ w0,
                                              const float* __restrict__ w1,
                                              const float* __restrict__ w2) {
    int i = blockIdx.x * 256 + threadIdx.x;
    int layer = i / 147456, rem = i - layer * 147456;
    const float* s = layer == 0 ? w0 : (layer == 1 ? w1 : w2);
    int tap = rem / 16384, rc = rem & 16383;
    int co = rc >> 7, ci = rc & 127;
    float v = s[(co * 128 + ci) * 9 + tap];
    __nv_bfloat16 hi = __float2bfloat16(v);
    __nv_bfloat16 lo = __float2bfloat16(v - __bfloat162float(hi));
    uint32_t off = (uint32_t)ci * 256 + ((((uint32_t)co >> 3) ^ ((uint32_t)ci & 7)) * 16)
                 + ((uint32_t)co & 7) * 2;
    char* base = (char*)g_WT + (size_t)(layer * 9 + tap) * 65536;
    *(__nv_bfloat16*)(base + off) = hi;
    *(__nv_bfloat16*)(base + 32768 + off) = lo;
}

__global__ __launch_bounds__(256) void wprep_dt1(const float* __restrict__ w) {
    int i = blockIdx.x * 256 + threadIdx.x;
    int ci = i >> 11, rem = i & 2047;
    int co = rem >> 4, k = rem & 15;
    int ky = k >> 2, kx = k & 3;
    int sy = 1 - (ky & 1), ty = (ky == 0 || ky == 3) ? 1 : 0;
    int sx = 1 - (kx & 1), tx = (kx == 0 || kx == 3) ? 1 : 0;
    int p = sy * 2 + sx, t = ty * 2 + tx;
    float v = w[i];
    __nv_bfloat16 hi = __float2bfloat16(v);
    __nv_bfloat16 lo = __float2bfloat16(v - __bfloat162float(hi));
    uint32_t off = (uint32_t)ci * 256 + ((((uint32_t)co >> 3) ^ ((uint32_t)ci & 7)) * 16)
                 + ((uint32_t)co & 7) * 2;
    char* base = (char*)g_WT + (size_t)(WT_DT1_BASE + (p * 4 + t) * 4096) * 16;
    *(__nv_bfloat16*)(base + off) = hi;
    *(__nv_bfloat16*)(base + 32768 + off) = lo;
}

__global__ __launch_bounds__(256) void cvt_nhwc(const float* __restrict__ src,
                                                __nv_bfloat16* __restrict__ hi,
                                                __nv_bfloat16* __restrict__ lo,
                                                int relu) {
    __shared__ __nv_bfloat16 sh[32][66], sl[32][66];
    const int p0 = blockIdx.x * 64, c0 = blockIdx.y * 32, b = blockIdx.z;
    const int t = threadIdx.x;
    #pragma unroll
    for (int it = 0; it < 8; it++) {
        int idx = t + it * 256;
        int c = idx >> 6, p = idx & 63;
        float v = src[((b * 128 + c0 + c) * 4096) + p0 + p];
        if (relu) v = fmaxf(v, 0.f);
        __nv_bfloat16 h = __float2bfloat16(v);
        sh[c][p] = h;
        sl[c][p] = __float2bfloat16(v - __bfloat162float(h));
    }
    __syncthreads();
    #pragma unroll
    for (int it = 0; it < 8; it++) {
        int idx = t + it * 256;
        int c = idx & 31, p = idx >> 5;
        size_t d = ((size_t)(b * 4096 + p0 + p) * 128) + c0 + c;
        hi[d] = sh[c][p];
        lo[d] = sl[c][p];
    }
}

// ---------------------------------------------------------------------------
// conv3x3 via mma.sync bf16 (decoder)
// ---------------------------------------------------------------------------
__global__ __launch_bounds__(256) void conv3x3_mma(
        const __nv_bfloat16* __restrict__ hi,
        const __nv_bfloat16* __restrict__ lo,
        const uint4* __restrict__ wt,
        const float* __restrict__ bias,
        float* __restrict__ out) {
    extern __shared__ char smem[];
    const uint32_t sbase = smem_u32(smem);
    const int tid = threadIdx.x;
    const int lane = tid & 31, warp = tid >> 5;
    const int b = blockIdx.x >> 5;
    const int y0 = (blockIdx.x & 31) * 2;
    const int mtile = (warp & 3) * 32;
    const int ntile = (warp >> 2) * 64;
    float* sb = (float*)(smem + 131072);
    if (tid < 128) sb[tid] = bias[tid];

    float acc[2][8][4];
    #pragma unroll
    for (int mi = 0; mi < 2; mi++)
        #pragma unroll
        for (int j = 0; j < 8; j++)
            #pragma unroll
            for (int q = 0; q < 4; q++) acc[mi][j][q] = 0.f;

    const int px = tid >> 1, half = tid & 1;
    const uint32_t rA = (uint32_t)(mtile + (lane & 15));
    const uint32_t cl = (uint32_t)(lane >> 4);
    const uint32_t swz = (uint32_t)(lane & 7);
    const uint32_t wrow = (uint32_t)((lane & 7) + ((lane >> 4) << 3));
    const uint32_t wq   = (uint32_t)((ntile >> 3) + ((lane >> 3) & 1));

    #pragma unroll 1
    for (int tap = 0; tap < 9; tap++) {
        const int dy = tap / 3 - 1, dx = tap % 3 - 1;
        __syncthreads();
        {
            const int yy = y0 + (px >> 6) + dy;
            const int xx = (px & 63) + dx;
            const bool valid = ((unsigned)yy < 64u) && ((unsigned)xx < 64u);
            const size_t rowoff = valid ? ((size_t)((b << 12) + yy * 64 + xx) * 128) : 0;
            const uint4* qh = (const uint4*)(hi + rowoff);
            const uint4* ql = (const uint4*)(lo + rowoff);
            uint4* AH = (uint4*)smem;
            uint4* AL = (uint4*)(smem + 32768);
            const uint4 z = make_uint4(0, 0, 0, 0);
            #pragma unroll
            for (int j = 0; j < 8; j++) {
                int cidx = half * 8 + j;
                int si = px * 16 + (cidx ^ (px & 7));
                AH[si] = valid ? qh[cidx] : z;
                AL[si] = valid ? ql[cidx] : z;
            }
        }
        {
            const uint4* wsrc = wt + (size_t)tap * 4096;
            uint4* WD = (uint4*)(smem + 65536);
            #pragma unroll
            for (int i = 0; i < 16; i++) WD[tid + i * 256] = wsrc[tid + i * 256];
        }
        __syncthreads();
        #pragma unroll 1
        for (int pass = 0; pass < 3; pass++) {
            const uint32_t Ab = sbase + (pass < 2 ? 0u : 32768u) + rA * 256u;
            const uint32_t Wb = sbase + 65536u + (pass == 1 ? 32768u : 0u);
            #pragma unroll
            for (int ks = 0; ks < 8; ks++) {
                const uint32_t ch = (((uint32_t)(2 * ks) + cl) ^ swz) * 16u;
                uint32_t a0[4], a1[4];
                ldsm_x4(a0, Ab + ch);
                ldsm_x4(a1, Ab + 4096u + ch);
                const uint32_t WbRow = Wb + ((uint32_t)ks * 16u + wrow) * 256u;
                uint32_t bf0[4], bf1[4], bf2[4], bf3[4];
                ldsm_x4t(bf0, WbRow + (((wq + 0u) ^ swz) * 16u));
                ldsm_x4t(bf1, WbRow + (((wq + 2u) ^ swz) * 16u));
                ldsm_x4t(bf2, WbRow + (((wq + 4u) ^ swz) * 16u));
                ldsm_x4t(bf3, WbRow + (((wq + 6u) ^ swz) * 16u));
                #pragma unroll
                for (int j = 0; j < 8; j++) {
                    const uint32_t* f = (j >> 1) == 0 ? bf0 : ((j >> 1) == 1 ? bf1 : ((j >> 1) == 2 ? bf2 : bf3));
                    uint32_t b0 = (j & 1) ? f[1] : f[0];
                    uint32_t b1 = (j & 1) ? f[3] : f[2];
                    mma16816(acc[0][j], a0, b0, b1);
                    mma16816(acc[1][j], a1, b0, b1);
                }
            }
        }
    }

    const int m_r = lane >> 2, n_c = (lane & 3) * 2;
    const int sp0 = y0 * 64;
    #pragma unroll
    for (int mi = 0; mi < 2; mi++) {
        #pragma unroll
        for (int j = 0; j < 8; j++) {
            int m = mtile + mi * 16 + m_r;
            int n = ntile + j * 8 + n_c;
            float* o0 = out + ((size_t)(b * 128 + n) << 12) + sp0 + m;
            float* o1 = o0 + 4096;
            o0[0] = acc[mi][j][0] + sb[n];
            o1[0] = acc[mi][j][1] + sb[n + 1];
            o0[8] = acc[mi][j][2] + sb[n];
            o1[8] = acc[mi][j][3] + sb[n + 1];
        }
    }
}

// ---------------------------------------------------------------------------
// dt1 via mma.sync bf16 (4 parity classes)
// ---------------------------------------------------------------------------
__global__ __launch_bounds__(256) void dt1_mma(
        const __nv_bfloat16* __restrict__ hi,
        const __nv_bfloat16* __restrict__ lo,
        const uint4* __restrict__ wtb,
        const float* __restrict__ bias,
        float* __restrict__ out) {
    extern __shared__ char smem[];
    const uint32_t sbase = smem_u32(smem);
    const int tid = threadIdx.x;
    const int lane = tid & 31, warp = tid >> 5;
    const int b = blockIdx.x >> 5;
    const int y0 = (blockIdx.x & 31) * 2;
    const int p = blockIdx.y;
    const int sy = p >> 1, sx = p & 1;
    const uint4* wt = wtb + (size_t)p * 4 * 4096;
    const int mtile = (warp & 3) * 32;
    const int ntile = (warp >> 2) * 64;
    float* sb = (float*)(smem + 131072);
    if (tid < 128) sb[tid] = bias[tid];

    float acc[2][8][4];
    #pragma unroll
    for (int mi = 0; mi < 2; mi++)
        #pragma unroll
        for (int j = 0; j < 8; j++)
            #pragma unroll
            for (int q = 0; q < 4; q++) acc[mi][j][q] = 0.f;

    const int px = tid >> 1, half = tid & 1;
    const uint32_t rA = (uint32_t)(mtile + (lane & 15));
    const uint32_t cl = (uint32_t)(lane >> 4);
    const uint32_t swz = (uint32_t)(lane & 7);
    const uint32_t wrow = (uint32_t)((lane & 7) + ((lane >> 4) << 3));
    const uint32_t wq   = (uint32_t)((ntile >> 3) + ((lane >> 3) & 1));

    #pragma unroll 1
    for (int t = 0; t < 4; t++) {
        const int ty = t >> 1, tx = t & 1;
        const int dy = ty == 0 ? 0 : (sy ? 1 : -1);
        const int dx = tx == 0 ? 0 : (sx ? 1 : -1);
        __syncthreads();
        {
            const int yy = y0 + (px >> 6) + dy;
            const int xx = (px & 63) + dx;
            const bool valid = ((unsigned)yy < 64u) && ((unsigned)xx < 64u);
            const size_t rowoff = valid ? ((size_t)((b << 12) + yy * 64 + xx) * 128) : 0;
            const uint4* qh = (const uint4*)(hi + rowoff);
            const uint4* ql = (const uint4*)(lo + rowoff);
            uint4* AH = (uint4*)smem;
            uint4* AL = (uint4*)(smem + 32768);
            const uint4 z = make_uint4(0, 0, 0, 0);
            #pragma unroll
            for (int j = 0; j < 8; j++) {
                int cidx = half * 8 + j;
                int si = px * 16 + (cidx ^ (px & 7));
                AH[si] = valid ? qh[cidx] : z;
                AL[si] = valid ? ql[cidx] : z;
            }
        }
        {
            const uint4* wsrc = wt + (size_t)t * 4096;
            uint4* WD = (uint4*)(smem + 65536);
            #pragma unroll
            for (int i = 0; i < 16; i++) WD[tid + i * 256] = wsrc[tid + i * 256];
        }
        __syncthreads();
        #pragma unroll 1
        for (int pass = 0; pass < 3; pass++) {
            const uint32_t Ab = sbase + (pass < 2 ? 0u : 32768u) + rA * 256u;
            const uint32_t Wb = sbase + 65536u + (pass == 1 ? 32768u : 0u);
            #pragma unroll
            for (int ks = 0; ks < 8; ks++) {
                const uint32_t ch = (((uint32_t)(2 * ks) + cl) ^ swz) * 16u;
                uint32_t a0[4], a1[4];
                ldsm_x4(a0, Ab + ch);
                ldsm_x4(a1, Ab + 4096u + ch);
                const uint32_t WbRow = Wb + ((uint32_t)ks * 16u + wrow) * 256u;
                uint32_t bf0[4], bf1[4], bf2[4], bf3[4];
                ldsm_x4t(bf0, WbRow + (((wq + 0u) ^ swz) * 16u));
                ldsm_x4t(bf1, WbRow + (((wq + 2u) ^ swz) * 16u));
                ldsm_x4t(bf2, WbRow + (((wq + 4u) ^ swz) * 16u));
                ldsm_x4t(bf3, WbRow + (((wq + 6u) ^ swz) * 16u));
                #pragma unroll
                for (int j = 0; j < 8; j++) {
                    const uint32_t* f = (j >> 1) == 0 ? bf0 : ((j >> 1) == 1 ? bf1 : ((j >> 1) == 2 ? bf2 : bf3));
                    uint32_t b0 = (j & 1) ? f[1] : f[0];
                    uint32_t b1 = (j & 1) ? f[3] : f[2];
                    mma16816(acc[0][j], a0, b0, b1);
                    mma16816(acc[1][j], a1, b0, b1);
                }
            }
        }
    }

    const int m_r = lane >> 2, n_c = (lane & 3) * 2;
    #pragma unroll
    for (int mi = 0; mi < 2; mi++) {
        #pragma unroll
        for (int j = 0; j < 8; j++) {
            int m = mtile + mi * 16 + m_r;
            int n = ntile + j * 8 + n_c;
            int qy = y0 + (m >> 6), qx = m & 63;
            size_t rowbase = ((size_t)(b * 128 + n) << 14) + (size_t)(2 * qy + sy) * 128 + sx;
            float* o0 = out + rowbase;
            float* o1 = o0 + 16384;
            float bn0 = sb[n], bn1 = sb[n + 1];
            o0[2*qx]        = fmaxf(acc[mi][j][0] + bn0, 0.f);
            o1[2*qx]        = fmaxf(acc[mi][j][1] + bn1, 0.f);
            o0[2*(qx + 8)]  = fmaxf(acc[mi][j][2] + bn0, 0.f);
            o1[2*(qx + 8)]  = fmaxf(acc[mi][j][3] + bn1, 0.f);
        }
    }
}

// ---------------------------------------------------------------------------
// e1: conv 3->128, k4 s2 p1, 256x256 -> 128x128, ReLU.
// Retiled: block = 128 threads (co), 8x8 output tile, x staged in smem.
// Per-acc FMA chain (ci->ky->kx asc, zero-padded borders) is bit-identical
// to the original per-thread kernel (fmaf(0,w,acc)==acc exactly).
// ---------------------------------------------------------------------------
__global__ __launch_bounds__(128) void e1_tile_k(const float* __restrict__ x,
                                                 const float* __restrict__ w,
                                                 const float* __restrict__ bias,
                                                 float* __restrict__ out) {
    const int co = threadIdx.x;
    const int ox0 = blockIdx.x * 8, oy0 = blockIdx.y * 8, b = blockIdx.z;
    __shared__ float s[3][18][20];   // padded rows (80B)
    __shared__ float sw[128*48];
    for (int i = co; i < 128*48; i += 128) sw[i] = w[i];
    const int iy0 = oy0*2 - 1, ix0 = ox0*2 - 1;
    for (int idx = co; idx < 3*324; idx += 128) {
        int ci = idx / 324, rr = idx % 324, r = rr / 18, cl = rr % 18;
        int iy = iy0 + r, ix = ix0 + cl;
        float v = 0.f;
        if ((unsigned)iy < 256u && (unsigned)ix < 256u)
            v = x[((b*3 + ci) << 16) + (iy << 8) + ix];
        s[ci][r][cl] = v;
    }
    __syncthreads();
    float acc[64];
    {
        float bv = bias[co];
        #pragma unroll
        for (int i = 0; i < 64; i++) acc[i] = bv;
    }
    #pragma unroll
    for (int ci = 0; ci < 3; ci++) {
        float wt[16];
        #pragma unroll
        for (int k = 0; k < 16; k++) wt[k] = sw[co*48 + ci*16 + k];
        #pragma unroll
        for (int r = 0; r < 18; r++) {
            float4 f0 = *(const float4*)&s[ci][r][0];
            float4 f1 = *(const float4*)&s[ci][r][4];
            float4 f2 = *(const float4*)&s[ci][r][8];
            float4 f3 = *(const float4*)&s[ci][r][12];
            float4 f4 = *(const float4*)&s[ci][r][16];
            float row[18] = {f0.x,f0.y,f0.z,f0.w, f1.x,f1.y,f1.z,f1.w,
                             f2.x,f2.y,f2.z,f2.w, f3.x,f3.y,f3.z,f3.w,
                             f4.x,f4.y};
            #pragma unroll
            for (int ky = 0; ky < 4; ky++) {
                if (((r - ky) & 1) == 0) {
                    int py = (r - ky) >> 1;
                    if (py >= 0 && py < 8) {
                        #pragma unroll
                        for (int px = 0; px < 8; px++) {
                            float a = acc[py*8 + px];
                            a = fmaf(row[2*px + 0], wt[ky*4 + 0], a);
                            a = fmaf(row[2*px + 1], wt[ky*4 + 1], a);
                            a = fmaf(row[2*px + 2], wt[ky*4 + 2], a);
                            a = fmaf(row[2*px + 3], wt[ky*4 + 3], a);
                            acc[py*8 + px] = a;
                        }
                    }
                }
            }
        }
    }
    float* op = out + (((b*128 + co) << 7) + oy0) * 128 + ox0;
    #pragma unroll
    for (int py = 0; py < 8; py++)
        #pragma unroll
        for (int px = 0; px < 8; px++)
            op[py*128 + px] = fmaxf(acc[py*8 + px], 0.f);
}

// ---------------------------------------------------------------------------
// e2: conv 128->128, k4 s2 p1 (scalar, encoder — bit-stable)
// ---------------------------------------------------------------------------
__global__ __launch_bounds__(128) void conv4s2_k(const float* __restrict__ in,
                                                 const float* __restrict__ wT,
                                                 const float* __restrict__ bias,
                                                 float* __restrict__ out) {
    const int co = threadIdx.x;
    const int ox0 = blockIdx.x * 8, oy0 = blockIdx.y * 8, b = blockIdx.z;
    __shared__ float s[8][18][20];
    float acc[64];
    {
        float bv = bias[co];
        #pragma unroll
        for (int i = 0; i < 64; i++) acc[i] = bv;
    }
    const int iy0 = oy0*2 - 1, ix0 = ox0*2 - 1;
    for (int cc = 0; cc < 128; cc += 8) {
        __syncthreads();
        for (int idx = co; idx < 8*324; idx += 128) {
            int ci = idx / 324, rr = idx % 324, r = rr / 18, cl = rr % 18;
            int iy = iy0 + r, ix = ix0 + cl;
            float v = 0.f;
            if ((unsigned)iy < 128u && (unsigned)ix < 128u)
                v = in[((b*128 + cc + ci) * 128 + iy) * 128 + ix];
            s[ci][r][cl] = v;
        }
        __syncthreads();
        #pragma unroll 1
        for (int ci = 0; ci < 8; ci++) {
            float wt[16];
            const float* wp = wT + (cc + ci) * 16 * 128 + co;
            #pragma unroll
            for (int k = 0; k < 16; k++) wt[k] = wp[k*128];
            #pragma unroll
            for (int r = 0; r < 18; r++) {
                float4 f0 = *(const float4*)&s[ci][r][0];
                float4 f1 = *(const float4*)&s[ci][r][4];
                float4 f2 = *(const float4*)&s[ci][r][8];
                float4 f3 = *(const float4*)&s[ci][r][12];
                float4 f4 = *(const float4*)&s[ci][r][16];
                float row[18] = {f0.x,f0.y,f0.z,f0.w, f1.x,f1.y,f1.z,f1.w,
                                 f2.x,f2.y,f2.z,f2.w, f3.x,f3.y,f3.z,f3.w,
                                 f4.x,f4.y};
                #pragma unroll
                for (int ky = 0; ky < 4; ky++) {
                    if (((r - ky) & 1) == 0) {
                        int py = (r - ky) >> 1;
                        if (py >= 0 && py < 8) {
                            #pragma unroll
                            for (int px = 0; px < 8; px++) {
                                float a = acc[py*8 + px];
                                a = fmaf(row[2*px + 0], wt[ky*4 + 0], a);
                                a = fmaf(row[2*px + 1], wt[ky*4 + 1], a);
                                a = fmaf(row[2*px + 2], wt[ky*4 + 2], a);
                                a = fmaf(row[2*px + 3], wt[ky*4 + 3], a);
                                acc[py*8 + px] = a;
                            }
                        }
                    }
                }
            }
        }
    }
    float* op = out + ((b*128 + co) * 64 + oy0) * 64 + ox0;
    #pragma unroll
    for (int py = 0; py < 8; py++)
        #pragma unroll
        for (int px = 0; px < 8; px++)
            op[py*64 + px] = fmaxf(acc[py*8 + px], 0.f);
}

// ---------------------------------------------------------------------------
// conv3x3 scalar (encoder), bit-identical
// ---------------------------------------------------------------------------
template<bool RELU_IN>
__global__ __launch_bounds__(128) void conv3x3_k(const float* __restrict__ in,
                                                 const float* __restrict__ wT,
                                                 const float* __restrict__ bias,
                                                 float* __restrict__ out) {
    const int co = threadIdx.x;
    const int ox0 = blockIdx.x * 8, oy0 = blockIdx.y * 8, b = blockIdx.z;
    __shared__ float s[16][10][12];
    float acc[64];
    {
        float bv = bias[co];
        #pragma unroll
        for (int i = 0; i < 64; i++) acc[i] = bv;
    }
    for (int cc = 0; cc < 128; cc += 16) {
        __syncthreads();
        for (int idx = co; idx < 16*100; idx += 128) {
            int ci = idx / 100, rr = idx % 100, r = rr / 10, cl = rr % 10;
            int iy = oy0 - 1 + r, ix = ox0 - 1 + cl;
            float v = 0.f;
            if ((unsigned)iy < 64u && (unsigned)ix < 64u) {
                v = in[((b*128 + cc + ci) * 64 + iy) * 64 + ix];
                if (RELU_IN) v = fmaxf(v, 0.f);
            }
            s[ci][r][cl] = v;
        }
        __syncthreads();
        #pragma unroll 1
        for (int ci = 0; ci < 16; ci++) {
            float wt[9];
            const float* wp = wT + (cc + ci) * 9 * 128 + co;
            #pragma unroll
            for (int k = 0; k < 9; k++) wt[k] = wp[k*128];
            #pragma unroll
            for (int r = 0; r < 10; r++) {
                float4 f0 = *(const float4*)&s[ci][r][0];
                float4 f1 = *(const float4*)&s[ci][r][4];
                float4 f2 = *(const float4*)&s[ci][r][8];
                float row[10] = {f0.x,f0.y,f0.z,f0.w, f1.x,f1.y,f1.z,f1.w,
                                 f2.x,f2.y};
                #pragma unroll
                for (int ky = 0; ky < 3; ky++) {
                    int py = r - ky;
                    if (py >= 0 && py < 8) {
                        #pragma unroll
                        for (int px = 0; px < 8; px++) {
                            float a = acc[py*8 + px];
                            a = fmaf(row[px + 0], wt[ky*3 + 0], a);
                            a = fmaf(row[px + 1], wt[ky*3 + 1], a);
                            a = fmaf(row[px + 2], wt[ky*3 + 2], a);
                            acc[py*8 + px] = a;
                        }
                    }
                }
            }
        }
    }
    float* op = out + ((b*128 + co) * 64 + oy0) * 64 + ox0;
    #pragma unroll
    for (int py = 0; py < 8; py++)
        #pragma unroll
        for (int px = 0; px < 8; px++)
            op[py*64 + px] = acc[py*8 + px];
}

// ---------------------------------------------------------------------------
// conv1x1 + input ReLU + residual
// ---------------------------------------------------------------------------
__global__ __launch_bounds__(128) void conv1x1_res_k(const float* __restrict__ in,
                                                     const float* __restrict__ wT,
                                                     const float* __restrict__ bias,
                                                     const float* __restrict__ res,
                                                     float* __restrict__ out) {
    const int co = threadIdx.x;
    const int b = blockIdx.x >> 6;
    const int p0 = (blockIdx.x & 63) * 64;
    __shared__ float s[32][64];
    float acc[64];
    {
        float bv = bias[co];
        #pragma unroll
        for (int i = 0; i < 64; i++) acc[i] = bv;
    }
    for (int cc = 0; cc < 128; cc += 32) {
        __syncthreads();
        for (int idx = co; idx < 32*64; idx += 128) {
            int ci = idx >> 6, p = idx & 63;
            float v = in[(b*128 + cc + ci) * 4096 + p0 + p];
            s[ci][p] = fmaxf(v, 0.f);
        }
        __syncthreads();
        #pragma unroll 1
        for (int ci = 0; ci < 32; ci++) {
            float wv = wT[(cc + ci) * 128 + co];
            const float4* sp = (const float4*)s[ci];
            #pragma unroll
            for (int p4 = 0; p4 < 16; p4++) {
                float4 v = sp[p4];
                acc[4*p4 + 0] = fmaf(v.x, wv, acc[4*p4 + 0]);
                acc[4*p4 + 1] = fmaf(v.y, wv, acc[4*p4 + 1]);
                acc[4*p4 + 2] = fmaf(v.z, wv, acc[4*p4 + 2]);
                acc[4*p4 + 3] = fmaf(v.w, wv, acc[4*p4 + 3]);
            }
        }
    }
    const float* rp = res + (b*128 + co) * 4096 + p0;
    float* op = out + (b*128 + co) * 4096 + p0;
    #pragma unroll
    for (int p = 0; p < 64; p++) op[p] = rp[p] + acc[p];
}

// ---------------------------------------------------------------------------
// VQ (reference-numerics replica) — unchanged
// ---------------------------------------------------------------------------
__global__ __launch_bounds__(256) void vq_k(const float* __restrict__ ze,
                                            const float* __restrict__ cb,
                                            float* __restrict__ zq) {
    const int b = blockIdx.x >> 6;
    const int p0 = (blockIdx.x & 63) * 64;
    __shared__ float zs[128][64];
    __shared__ float cs[16][128];
    __shared__ float zzs[64];
    __shared__ float ees[512];
    __shared__ float rb1[256]; __shared__ int ri1[256];
    __shared__ int   finalidx[64];
    const int t = threadIdx.x;
    const float* zb = ze + b * 128 * 4096 + p0;
    for (int idx = t; idx < 128*64; idx += 256) {
        int c = idx >> 6, p = idx & 63;
        zs[c][p] = zb[c*4096 + p];
    }
    for (int k = t; k < 512; k += 256) {
        const float* cp = cb + k * 128;
        double acc = 0.0;
        for (int c = 0; c < 128; c++) { double e = (double)cp[c]; acc += e * e; }
        ees[k] = (float)acc;
    }
    __syncthreads();
    if (t < 64) {
        double acc = 0.0;
        for (int c = 0; c < 128; c++) { double z = (double)zs[c][t]; acc += z * z; }
        zzs[t] = (float)acc;
    }
    __syncthreads();

    float b1 = 3.4e38f; int i1 = 0x7fffffff;
    const int pos = t & 63, cg = t >> 6;
    const float zz = zzs[pos];
    for (int k0 = 0; k0 < 512; k0 += 16) {
        __syncthreads();
        for (int idx = t; idx < 16*128; idx += 256)
            cs[idx >> 7][idx & 127] = cb[k0*128 + idx];
        __syncthreads();
        float dot0 = 0.f, dot1 = 0.f, dot2 = 0.f, dot3 = 0.f;
        const float4* e0 = (const float4*)cs[cg + 0];
        const float4* e1 = (const float4*)cs[cg + 4];
        const float4* e2 = (const float4*)cs[cg + 8];
        const float4* e3 = (const float4*)cs[cg + 12];
        #pragma unroll 4
        for (int c4 = 0; c4 < 32; c4++) {
            float z0 = zs[4*c4 + 0][pos];
            float z1 = zs[4*c4 + 1][pos];
            float z2 = zs[4*c4 + 2][pos];
            float z3 = zs[4*c4 + 3][pos];
            float4 a = e0[c4], bb = e1[c4], cA = e2[c4], dd = e3[c4];
            dot0 = __fmaf_rn(z0, a.x, dot0);  dot0 = __fmaf_rn(z1, a.y, dot0);
            dot0 = __fmaf_rn(z2, a.z, dot0);  dot0 = __fmaf_rn(z3, a.w, dot0);
            dot1 = __fmaf_rn(z0, bb.x, dot1); dot1 = __fmaf_rn(z1, bb.y, dot1);
            dot1 = __fmaf_rn(z2, bb.z, dot1); dot1 = __fmaf_rn(z3, bb.w, dot1);
            dot2 = __fmaf_rn(z0, cA.x, dot2); dot2 = __fmaf_rn(z1, cA.y, dot2);
            dot2 = __fmaf_rn(z2, cA.z, dot2); dot2 = __fmaf_rn(z3, cA.w, dot2);
            dot3 = __fmaf_rn(z0, dd.x, dot3); dot3 = __fmaf_rn(z1, dd.y, dot3);
            dot3 = __fmaf_rn(z2, dd.z, dot3); dot3 = __fmaf_rn(z3, dd.w, dot3);
        }
        float dts[4] = {dot0, dot1, dot2, dot3};
        #pragma unroll
        for (int m = 0; m < 4; m++) {
            int gidx = k0 + cg + 4*m;
            float d = __fadd_rn(__fsub_rn(zz, __fmul_rn(2.f, dts[m])), ees[gidx]);
            if (d < b1) { b1 = d; i1 = gidx; }
        }
    }
    rb1[t] = b1; ri1[t] = i1;
    __syncthreads();
    if (t < 64) {
        float B1 = rb1[t]; int I1 = ri1[t];
        #pragma unroll
        for (int g = 1; g < 4; g++) {
            float v = rb1[t + 64*g]; int vi = ri1[t + 64*g];
            if (v < B1 || (v == B1 && vi < I1)) { B1 = v; I1 = vi; }
        }
        finalidx[t] = I1;
    }
    __syncthreads();
    float* zqb = zq + b * 128 * 4096 + p0;
    for (int idx = t; idx < 128*64; idx += 256) {
        int c = idx >> 6, p = idx & 63;
        zqb[c*4096 + p] = cb[finalidx[p]*128 + c];
    }
}

// ---------------------------------------------------------------------------
// dt2: ConvTranspose2d 128->3, k4 s2 p1, 128x128 -> 256x256
// ---------------------------------------------------------------------------
__global__ __launch_bounds__(256) void dt2_k(const float* __restrict__ in,
                                             const float* __restrict__ w,
                                             const float* __restrict__ bias,
                                             float* __restrict__ out) {
    __shared__ float ws[128*3*16];
    for (int i = threadIdx.x; i < 128*3*16; i += 256) ws[i] = w[i];
    __syncthreads();
    int g = blockIdx.x * 256 + threadIdx.x;
    int ox = g & 255, oy = (g >> 8) & 255, b = g >> 16;
    float a0 = bias[0], a1 = bias[1], a2 = bias[2];
    const int ky0 = (oy + 1) & 1, kx0 = (ox + 1) & 1;
    const int iyh = (oy + 1 - ky0) >> 1, ixh = (ox + 1 - kx0) >> 1;
    #pragma unroll 4
    for (int ci = 0; ci < 128; ci++) {
        const float* ip = in + ((b*128 + ci) << 14);
        const float* wp = ws + ci * 48;
        #pragma unroll
        for (int dy = 0; dy < 2; dy++) {
            int iy = iyh - dy, ky = ky0 + 2*dy;
            if ((unsigned)iy < 128u) {
                #pragma unroll
                for (int dx = 0; dx < 2; dx++) {
                    int ix = ixh - dx, kx = kx0 + 2*dx;
                    if ((unsigned)ix < 128u) {
                        float v = ip[iy*128 + ix];
                        int wk = ky*4 + kx;
                        a0 = fmaf(v, wp[wk],      a0);
                        a1 = fmaf(v, wp[16 + wk], a1);
                        a2 = fmaf(v, wp[32 + wk], a2);
                    }
                }
            }
        }
    }
    int sp = oy*256 + ox;
    out[(b*3 + 0) * 65536 + sp] = a0;
    out[(b*3 + 1) * 65536 + sp] = a1;
    out[(b*3 + 2) * 65536 + sp] = a2;
}

// ---------------------------------------------------------------------------

extern "C" void kernel_launch(void* const* d_in, const int* in_sizes, int n_in,
                              void* d_out, int out_size) {
    const float* x      = (const float*)d_in[0];
    const float* e1_w   = (const float*)d_in[1];  const float* e1_b = (const float*)d_in[2];
    const float* e2_w   = (const float*)d_in[3];  const float* e2_b = (const float*)d_in[4];
    const float* e3_w   = (const float*)d_in[5];  const float* e3_b = (const float*)d_in[6];
    const float* er1a_w = (const float*)d_in[7];  const float* er1a_b = (const float*)d_in[8];
    const float* er1b_w = (const float*)d_in[9];  const float* er1b_b = (const float*)d_in[10];
    const float* er2a_w = (const float*)d_in[11]; const float* er2a_b = (const float*)d_in[12];
    const float* er2b_w = (const float*)d_in[13]; const float* er2b_b = (const float*)d_in[14];
    const float* codebook = (const float*)d_in[15];
    const float* d1_w   = (const float*)d_in[16]; const float* d1_b = (const float*)d_in[17];
    const float* dr1a_w = (const float*)d_in[18]; const float* dr1a_b = (const float*)d_in[19];
    const float* dr1b_w = (const float*)d_in[20]; const float* dr1b_b = (const float*)d_in[21];
    const float* dr2a_w = (const float*)d_in[22]; const float* dr2a_b = (const float*)d_in[23];
    const float* dr2b_w = (const float*)d_in[24]; const float* dr2b_b = (const float*)d_in[25];
    const float* dt1_w  = (const float*)d_in[26]; const float* dt1_b = (const float*)d_in[27];
    const float* dt2_w  = (const float*)d_in[28]; const float* dt2_b = (const float*)d_in[29];

    float* out   = (float*)d_out;
    float* xhat  = out;
    float* ze    = out + XHAT_ELEMS;
    float* zq    = out + XHAT_ELEMS + ZE_ELEMS;

    float* A;  cudaGetSymbolAddress((void**)&A,  g_A);
    float* Bf; cudaGetSymbolAddress((void**)&Bf, g_B);
    float* Cf; cudaGetSymbolAddress((void**)&Cf, g_C);
    float* Df; cudaGetSymbolAddress((void**)&Df, g_D);
    float* Tf; cudaGetSymbolAddress((void**)&Tf, g_T);
    float* W;  cudaGetSymbolAddress((void**)&W,  g_W);
    __nv_bfloat16* Hi; cudaGetSymbolAddress((void**)&Hi, g_Hi);
    __nv_bfloat16* Lo; cudaGetSymbolAddress((void**)&Lo, g_Lo);
    uint4* WT; cudaGetSymbolAddress((void**)&WT, g_WT);

    cudaFuncSetAttribute(conv3x3_mma, cudaFuncAttributeMaxDynamicSharedMemorySize, 131584);
    cudaFuncSetAttribute(dt1_mma, cudaFuncAttributeMaxDynamicSharedMemorySize, 131584);

    // weight prep
    tpose_all<<<4032, 256>>>(e3_w, er1a_w, er2a_w, e2_w, dt1_w,
                             er1b_w, er2b_w, dr1b_w, dr2b_w, W);
    wprep3<<<1728, 256>>>(d1_w, dr1a_w, dr2a_w);
    wprep_dt1<<<1024, 256>>>(dt1_w);

    dim3 tile64(8, 8, BATCH);
    dim3 tile128(16, 16, BATCH);
    dim3 cvtg(64, 4, 16);
    dim3 dt1g(16*32, 4);

    // encoder (scalar, bit-identical)
    e1_tile_k<<<tile128, 128>>>(x, e1_w, e1_b, A);
    conv4s2_k<<<tile64, 128>>>(A, W + WE2_OFF, e2_b, Bf);
    conv3x3_k<false><<<tile64, 128>>>(Bf, W + W3_OFF(0), e3_b, Cf);
    conv3x3_k<true><<<tile64, 128>>>(Cf, W + W3_OFF(1), er1a_b, Tf);
    conv1x1_res_k<<<16*64, 128>>>(Tf, W + W1_OFF(0), er1b_b, Cf, Df);
    conv3x3_k<true><<<tile64, 128>>>(Df, W + W3_OFF(2), er2a_b, Tf);
    conv1x1_res_k<<<16*64, 128>>>(Tf, W + W1_OFF(1), er2b_b, Df, ze);
    // VQ
    vq_k<<<16*64, 256>>>(ze, codebook, zq);
    // decoder: mma tensor cores
    cvt_nhwc<<<cvtg, 256>>>(zq, Hi, Lo, 0);
    conv3x3_mma<<<512, 256, 131584>>>(Hi, Lo, WT + (size_t)0*9*4096, d1_b, Cf);
    cvt_nhwc<<<cvtg, 256>>>(Cf, Hi, Lo, 1);
    conv3x3_mma<<<512, 256, 131584>>>(Hi, Lo, WT + (size_t)1*9*4096, dr1a_b, Tf);
    conv1x1_res_k<<<16*64, 128>>>(Tf, W + W1_OFF(2), dr1b_b, Cf, Df);
    cvt_nhwc<<<cvtg, 256>>>(Df, Hi, Lo, 1);
    conv3x3_mma<<<512, 256, 131584>>>(Hi, Lo, WT + (size_t)2*9*4096, dr2a_b, Tf);
    conv1x1_res_k<<<16*64, 128>>>(Tf, W + W1_OFF(3), dr2b_b, Df, Bf);
    cvt_nhwc<<<cvtg, 256>>>(Bf, Hi, Lo, 0);
    dt1_mma<<<dt1g, 256, 131584>>>(Hi, Lo, WT + WT_DT1_BASE, dt1_b, A);
    dt2_k<<<(16*256*256)/256, 256>>>(A, dt2_w, dt2_b, xhat);
}